// round 4
// baseline (speedup 1.0000x reference)
#include <cuda_runtime.h>
#include <math.h>

// ---------------- problem constants ----------------
#define BB   16
#define C1   64
#define T1   4096
#define CO   32
#define T2   2048      // after GLU over time
#define T3   2019      // after depthwise conv k=32, pad(1,1)
#define HH   64        // d_model
#define NST  64        // S4 state size
#define NL   8
#define DOUT 640
#define EPSF 1e-5f

// ---------------- scratch (device globals; no allocation) ----------------
__device__ float g_u1[BB*CO*T1];     // pw1 output
__device__ float g_ug[BB*CO*T2];     // after GLU+SiLU
__device__ float g_u2[BB*CO*T3];     // after depthwise conv (+bias)
__device__ float g_h [BB*HH*T3];     // running hidden state
__device__ float g_y [BB*HH*T3];     // s4 conv+gelu output
__device__ float g_st1[BB*2];        // GN1 sum/sumsq per batch
__device__ float g_st2[BB*2];        // GN2 sum/sumsq per batch
__device__ float g_Wm [HH*CO];       // fused enc∘pw2 matrix
__device__ float g_bv [HH];          // fused bias
__device__ float g_ar[HH*NST];       // per-layer discrete a (real)
__device__ float g_ai[HH*NST];
__device__ float g_cr[HH*NST];       // 2*Cd (real)
__device__ float g_ci[HH*NST];

// ---------------- tiny zero kernel (stats buffers) ----------------
__global__ void k_zero() {
    int i = threadIdx.x;
    if (i < BB*2) { g_st1[i] = 0.f; g_st2[i] = 0.f; }
}

// ---------------- pw1 (64->32 pointwise) + GN1 stats ----------------
__global__ __launch_bounds__(256) void k_pw1(const float* __restrict__ x,
                                             const float* __restrict__ w,
                                             const float* __restrict__ bias) {
    __shared__ float xs[C1][128];
    __shared__ float ws[CO][C1];
    __shared__ float rs[8], rss[8];
    int b = blockIdx.y, t0 = blockIdx.x * 128;
    int tid = threadIdx.x;
    for (int i = tid; i < C1*128; i += 256) {
        int c = i >> 7, tt = i & 127;
        xs[c][tt] = x[(b*C1 + c)*T1 + t0 + tt];
    }
    for (int i = tid; i < CO*C1; i += 256) ws[i >> 6][i & 63] = w[i];
    __syncthreads();
    int tt = tid & 127, half = tid >> 7;
    float acc[16];
#pragma unroll
    for (int og = 0; og < 16; og++) acc[og] = bias[half*16 + og];
    for (int c = 0; c < C1; c++) {
        float xv = xs[c][tt];
#pragma unroll
        for (int og = 0; og < 16; og++)
            acc[og] = fmaf(ws[half*16 + og][c], xv, acc[og]);
    }
    float s = 0.f, ss = 0.f;
#pragma unroll
    for (int og = 0; og < 16; og++) {
        int o = half*16 + og;
        g_u1[(b*CO + o)*T1 + t0 + tt] = acc[og];
        s += acc[og]; ss += acc[og]*acc[og];
    }
#pragma unroll
    for (int off = 16; off; off >>= 1) {
        s  += __shfl_xor_sync(0xffffffffu, s,  off);
        ss += __shfl_xor_sync(0xffffffffu, ss, off);
    }
    int wid = tid >> 5;
    if ((tid & 31) == 0) { rs[wid] = s; rss[wid] = ss; }
    __syncthreads();
    if (tid == 0) {
        float a = 0.f, q = 0.f;
        for (int i = 0; i < 8; i++) { a += rs[i]; q += rss[i]; }
        atomicAdd(&g_st1[b*2],     a);
        atomicAdd(&g_st1[b*2 + 1], q);
    }
}

// ---------------- GN1 apply + GLU(time) + SiLU ----------------
__global__ __launch_bounds__(256) void k_glu(const float* __restrict__ g1,
                                             const float* __restrict__ b1) {
    int idx = blockIdx.x * 256 + threadIdx.x;     // b*CO*T2 elements
    int t = idx & (T2 - 1);
    int c = (idx >> 11) & (CO - 1);
    int b = idx >> 16;                            // 2048*32 = 65536
    float n = (float)(CO * T1);
    float m   = g_st1[b*2] / n;
    float var = g_st1[b*2 + 1] / n - m*m;
    float rstd = rsqrtf(var + EPSF);
    float sc = rstd * g1[c], sh = b1[c] - m * rstd * g1[c];
    const float* base = g_u1 + (b*CO + c)*T1;
    float ga = fmaf(base[t],        sc, sh);
    float gb = fmaf(base[t + T2],   sc, sh);
    float v = ga / (1.f + expf(-gb));   // GLU
    v = v / (1.f + expf(-v));           // SiLU
    g_ug[idx] = v;
}

// ---------------- depthwise conv (k=32, pad 1) + GN2 stats ----------------
__global__ __launch_bounds__(256) void k_dw(const float* __restrict__ w,
                                            const float* __restrict__ bias) {
    __shared__ float us[256 + 31];
    __shared__ float wk[32];
    __shared__ float rs[8], rss[8];
    int t0 = blockIdx.x * 256, c = blockIdx.y, b = blockIdx.z;
    int tid = threadIdx.x;
    if (tid < 32) wk[tid] = w[c*32 + tid];
    const float* src = g_ug + (b*CO + c)*T2;
    int base = t0 - 1;
    for (int i = tid; i < 287; i += 256) {
        int gi = base + i;
        us[i] = (gi >= 0 && gi < T2) ? src[gi] : 0.f;
    }
    __syncthreads();
    int t = t0 + tid;
    float acc = bias[c];
    bool valid = (t < T3);
    if (valid) {
#pragma unroll
        for (int k = 0; k < 32; k++) acc = fmaf(wk[k], us[tid + k], acc);
        g_u2[(b*CO + c)*T3 + t] = acc;
    }
    float s = valid ? acc : 0.f, ss = s*acc*(valid ? 1.f : 0.f);
    ss = valid ? acc*acc : 0.f;
#pragma unroll
    for (int off = 16; off; off >>= 1) {
        s  += __shfl_xor_sync(0xffffffffu, s,  off);
        ss += __shfl_xor_sync(0xffffffffu, ss, off);
    }
    int wid = tid >> 5;
    if ((tid & 31) == 0) { rs[wid] = s; rss[wid] = ss; }
    __syncthreads();
    if (tid == 0) {
        float a = 0.f, q = 0.f;
        for (int i = 0; i < 8; i++) { a += rs[i]; q += rss[i]; }
        atomicAdd(&g_st2[b*2],     a);
        atomicAdd(&g_st2[b*2 + 1], q);
    }
}

// ---------------- precompute fused (enc ∘ pw2) matrix ----------------
__global__ void k_prep(const float* __restrict__ pw2w, const float* __restrict__ pw2b,
                       const float* __restrict__ encw, const float* __restrict__ encb) {
    int tid = threadIdx.x;
    for (int i = tid; i < HH*CO; i += 256) {
        int d = i >> 5, cp = i & 31;
        float acc = 0.f;
        for (int c = 0; c < CO; c++)
            acc = fmaf(encw[c*HH + d], pw2w[c*CO + cp], acc);
        g_Wm[i] = acc;
    }
    if (tid < HH) {
        float acc = encb[tid];
        for (int c = 0; c < CO; c++)
            acc = fmaf(encw[c*HH + tid], pw2b[c], acc);
        g_bv[tid] = acc;
    }
}

// ---------------- GN2 apply + fused pw2∘enc -> h ----------------
__global__ __launch_bounds__(256) void k_enc(const float* __restrict__ g2,
                                             const float* __restrict__ b2) {
    __shared__ float un[CO][128];
    __shared__ float Ws[HH][CO];
    int b = blockIdx.y, t0 = blockIdx.x * 128;
    int tid = threadIdx.x;
    float n = (float)(CO * T3);
    float m   = g_st2[b*2] / n;
    float var = g_st2[b*2 + 1] / n - m*m;
    float rstd = rsqrtf(var + EPSF);
    for (int i = tid; i < CO*128; i += 256) {
        int c = i >> 7, tt = i & 127;
        int t = t0 + tt;
        float v = (t < T3) ? g_u2[(b*CO + c)*T3 + t] : 0.f;
        un[c][tt] = (v - m) * rstd * g2[c] + b2[c];
    }
    for (int i = tid; i < HH*CO; i += 256) Ws[i >> 5][i & 31] = g_Wm[i];
    __syncthreads();
    int tt = tid & 127, dg = tid >> 7;
    float acc[32];
#pragma unroll
    for (int dd = 0; dd < 32; dd++) acc[dd] = g_bv[dg*32 + dd];
    for (int c = 0; c < CO; c++) {
        float uv = un[c][tt];
#pragma unroll
        for (int dd = 0; dd < 32; dd++)
            acc[dd] = fmaf(Ws[dg*32 + dd][c], uv, acc[dd]);
    }
    int t = t0 + tt;
    if (t < T3)
#pragma unroll
        for (int dd = 0; dd < 32; dd++)
            g_h[(b*HH + dg*32 + dd)*T3 + t] = acc[dd];
}

// ---------------- per-layer S4D discretization constants ----------------
__global__ void k_s4c(const float* __restrict__ logdt, const float* __restrict__ logA,
                      const float* __restrict__ Aim,  const float* __restrict__ Cre,
                      const float* __restrict__ Cim, int lay) {
    int h = blockIdx.x, n = threadIdx.x;
    int hn = h*NST + n;
    int src = (lay*HH + h)*NST + n;
    float dt  = expf(logdt[lay*HH + h]);
    float Are = -expf(logA[src]);
    float Aii = Aim[src];
    float xre = Are * dt, xim = Aii * dt;
    float e = expf(xre);
    float are = e * cosf(xim);
    float aim = e * sinf(xim);
    // (a - 1) / A
    float nre = are - 1.f, nim = aim;
    float den = Are*Are + Aii*Aii;
    float qre = (nre*Are + nim*Aii) / den;
    float qim = (nim*Are - nre*Aii) / den;
    float cre = Cre[src], cim = Cim[src];
    float cr = cre*qre - cim*qim;
    float ci = cre*qim + cim*qre;
    g_ar[hn] = are; g_ai[hn] = aim;
    g_cr[hn] = 2.f*cr; g_ci[hn] = 2.f*ci;
}

// ---------------- S4D scan: recurrence conv + D skip + GELU ----------------
__global__ __launch_bounds__(128) void k_scan(const float* __restrict__ D, int lay) {
    __shared__ float us[4][32];
    __shared__ float ps[4][32*33];
    int lane = threadIdx.x & 31, wl = threadIdx.x >> 5;
    int gw = blockIdx.x * 4 + wl;            // 0..1023
    int b = gw >> 6, h = gw & 63;
    float* psw = ps[wl];
    float* usw = us[wl];
    int n1 = lane, n2 = lane + 32;
    float a1r = g_ar[h*NST + n1], a1i = g_ai[h*NST + n1];
    float a2r = g_ar[h*NST + n2], a2i = g_ai[h*NST + n2];
    float c1r = g_cr[h*NST + n1], c1i = g_ci[h*NST + n1];
    float c2r = g_cr[h*NST + n2], c2i = g_ci[h*NST + n2];
    float Dh = D[lay*HH + h];
    const float* uin = g_h + (b*HH + h)*T3;
    float* yo = g_y + (b*HH + h)*T3;
    float s1r = 0.f, s1i = 0.f, s2r = 0.f, s2i = 0.f;
    for (int c0 = 0; c0 < T3; c0 += 32) {
        int len = min(32, T3 - c0);
        float uval = (lane < len) ? uin[c0 + lane] : 0.f;
        usw[lane] = uval;
        __syncwarp();
        if (len == 32) {
#pragma unroll
            for (int j = 0; j < 32; j++) {
                float u = usw[j];
                float t1  = fmaf(-a1i, s1i, u);
                float n1r = fmaf(a1r, s1r, t1);
                float n1i = fmaf(a1r, s1i, a1i*s1r);
                float t2  = fmaf(-a2i, s2i, u);
                float n2r = fmaf(a2r, s2r, t2);
                float n2i = fmaf(a2r, s2i, a2i*s2r);
                s1r = n1r; s1i = n1i; s2r = n2r; s2i = n2i;
                float p = fmaf(c1r, s1r, fmaf(-c1i, s1i, fmaf(c2r, s2r, -c2i*s2i)));
                psw[lane*33 + j] = p;
            }
        } else {
            for (int j = 0; j < len; j++) {
                float u = usw[j];
                float t1  = fmaf(-a1i, s1i, u);
                float n1r = fmaf(a1r, s1r, t1);
                float n1i = fmaf(a1r, s1i, a1i*s1r);
                float t2  = fmaf(-a2i, s2i, u);
                float n2r = fmaf(a2r, s2r, t2);
                float n2i = fmaf(a2r, s2i, a2i*s2r);
                s1r = n1r; s1i = n1i; s2r = n2r; s2i = n2i;
                float p = fmaf(c1r, s1r, fmaf(-c1i, s1i, fmaf(c2r, s2r, -c2i*s2i)));
                psw[lane*33 + j] = p;
            }
        }
        __syncwarp();
        if (lane < len) {
            float acc = 0.f;
#pragma unroll
            for (int k = 0; k < 32; k++) acc += psw[k*33 + lane];
            float yv = fmaf(Dh, usw[lane], acc);
            yv = 0.5f * yv * (1.f + erff(yv * 0.70710678118f));  // exact GELU
            yo[c0 + lane] = yv;
        }
        __syncwarp();
    }
}

// ---------------- mixer: ow GEMM + GLU(channel) + residual + LN(channel) ----------------
__global__ __launch_bounds__(256) void k_mix(const float* __restrict__ ow,
                                             const float* __restrict__ ob,
                                             const float* __restrict__ lg,
                                             const float* __restrict__ lb, int lay) {
    __shared__ float ys[HH][33];
    __shared__ float hs[HH][33];
    __shared__ float zs[HH][33];
    __shared__ float rsum[8][32], rss[8][32];
    __shared__ float mu[32], rstd[32];
    int b = blockIdx.y, t0 = blockIdx.x * 32;
    int tid = threadIdx.x;
    int lane = tid & 31, w = tid >> 5;
    int len = min(32, T3 - t0);
    for (int i = tid; i < HH*32; i += 256) {
        int ch = i >> 5, tt = i & 31;
        float yv = 0.f, hv = 0.f;
        if (tt < len) {
            yv = g_y[(b*HH + ch)*T3 + t0 + tt];
            hv = g_h[(b*HH + ch)*T3 + t0 + tt];
        }
        ys[ch][tt] = yv; hs[ch][tt] = hv;
    }
    __syncthreads();
    const float* owl = ow + lay*2*HH*HH;
    const float* obl = ob + lay*2*HH;
    float ls = 0.f, lss = 0.f;
#pragma unroll
    for (int it = 0; it < 8; it++) {
        int j = w*8 + it;
        float a1 = obl[j], a2 = obl[j + HH];
        const float* r1 = owl + j*HH;
        const float* r2 = owl + (j + HH)*HH;
        for (int hh = 0; hh < HH; hh++) {
            float yv = ys[hh][lane];
            a1 = fmaf(r1[hh], yv, a1);
            a2 = fmaf(r2[hh], yv, a2);
        }
        float z = a1 / (1.f + expf(-a2));    // channel GLU
        float v = z + hs[j][lane];           // residual
        zs[j][lane] = v;
        ls += v; lss += v*v;
    }
    rsum[w][lane] = ls; rss[w][lane] = lss;
    __syncthreads();
    if (w == 0) {
        float s = 0.f, ss = 0.f;
#pragma unroll
        for (int k = 0; k < 8; k++) { s += rsum[k][lane]; ss += rss[k][lane]; }
        float m = s / 64.f;
        float var = ss / 64.f - m*m;
        mu[lane] = m; rstd[lane] = rsqrtf(var + EPSF);
    }
    __syncthreads();
    if (lane < len) {
        float m = mu[lane], r = rstd[lane];
#pragma unroll
        for (int it = 0; it < 8; it++) {
            int j = w*8 + it;
            float gval = lg[lay*HH + j], bval = lb[lay*HH + j];
            g_h[(b*HH + j)*T3 + t0 + lane] = (zs[j][lane] - m) * r * gval + bval;
        }
    }
}

// ---------------- decoder: (b,d,t) x (d,o) -> (b,t,o) ----------------
__global__ __launch_bounds__(256) void k_dec(const float* __restrict__ dw,
                                             const float* __restrict__ db,
                                             float* __restrict__ out) {
    __shared__ float hsd[HH][32];
    int o0 = blockIdx.x * 64, t0 = blockIdx.y * 32, b = blockIdx.z;
    int tid = threadIdx.x;
    int len = min(32, T3 - t0);
    for (int i = tid; i < HH*32; i += 256) {
        int d = i >> 5, tt = i & 31;
        hsd[d][tt] = (tt < len) ? g_h[(b*HH + d)*T3 + t0 + tt] : 0.f;
    }
    __syncthreads();
    int o = o0 + (tid & 63);
    int tq = tid >> 6;              // 4 groups x 8 t
    float acc[8];
    float bo = db[o];
#pragma unroll
    for (int r = 0; r < 8; r++) acc[r] = bo;
    for (int d = 0; d < HH; d++) {
        float wv = dw[d*DOUT + o];
        const float4* hp = reinterpret_cast<const float4*>(&hsd[d][tq*8]);
        float4 v0 = hp[0], v1 = hp[1];
        acc[0] = fmaf(wv, v0.x, acc[0]);
        acc[1] = fmaf(wv, v0.y, acc[1]);
        acc[2] = fmaf(wv, v0.z, acc[2]);
        acc[3] = fmaf(wv, v0.w, acc[3]);
        acc[4] = fmaf(wv, v1.x, acc[4]);
        acc[5] = fmaf(wv, v1.y, acc[5]);
        acc[6] = fmaf(wv, v1.z, acc[6]);
        acc[7] = fmaf(wv, v1.w, acc[7]);
    }
#pragma unroll
    for (int r = 0; r < 8; r++) {
        int t = t0 + tq*8 + r;
        if (t < T3) out[(b*T3 + t)*DOUT + o] = acc[r];
    }
}

// ---------------- launcher ----------------
extern "C" void kernel_launch(void* const* d_in, const int* in_sizes, int n_in,
                              void* d_out, int out_size) {
    const float* x      = (const float*)d_in[0];
    const float* pw1w   = (const float*)d_in[1];
    const float* pw1b   = (const float*)d_in[2];
    const float* gn1g   = (const float*)d_in[3];
    const float* gn1b   = (const float*)d_in[4];
    const float* dww    = (const float*)d_in[5];
    const float* dwb    = (const float*)d_in[6];
    const float* gn2g   = (const float*)d_in[7];
    const float* gn2b   = (const float*)d_in[8];
    const float* pw2w   = (const float*)d_in[9];
    const float* pw2b   = (const float*)d_in[10];
    const float* encw   = (const float*)d_in[11];
    const float* encb   = (const float*)d_in[12];
    const float* logdt  = (const float*)d_in[13];
    const float* logA   = (const float*)d_in[14];
    const float* Aim    = (const float*)d_in[15];
    const float* Cre    = (const float*)d_in[16];
    const float* Cim    = (const float*)d_in[17];
    const float* s4D    = (const float*)d_in[18];
    const float* s4ow   = (const float*)d_in[19];
    const float* s4ob   = (const float*)d_in[20];
    const float* lng    = (const float*)d_in[21];
    const float* lnb    = (const float*)d_in[22];
    const float* decw   = (const float*)d_in[23];
    const float* decb   = (const float*)d_in[24];
    float* out = (float*)d_out;

    k_zero<<<1, 64>>>();
    k_pw1<<<dim3(T1/128, BB), 256>>>(x, pw1w, pw1b);
    k_glu<<<(BB*CO*T2)/256, 256>>>(gn1g, gn1b);
    k_dw<<<dim3(8, CO, BB), 256>>>(dww, dwb);
    k_prep<<<1, 256>>>(pw2w, pw2b, encw, encb);
    k_enc<<<dim3(16, BB), 256>>>(gn2g, gn2b);
    for (int l = 0; l < NL; l++) {
        k_s4c<<<HH, NST>>>(logdt, logA, Aim, Cre, Cim, l);
        k_scan<<<256, 128>>>(s4D, l);
        k_mix<<<dim3(64, BB), 256>>>(s4ow, s4ob, lng, lnb, l);
    }
    k_dec<<<dim3(DOUT/64, 64, BB), 256>>>(decw, decb, out);
}

// round 5
// speedup vs baseline: 1.1785x; 1.1785x over previous
#include <cuda_runtime.h>
#include <math.h>

typedef unsigned long long ull;

// ---------------- problem constants ----------------
#define BB   16
#define C1   64
#define T1   4096
#define CO   32
#define T2   2048      // after GLU over time
#define T3   2019      // after depthwise conv k=32, pad(1,1)
#define HH   64        // d_model
#define NST  64        // S4 state size
#define NL   8
#define DOUT 640
#define EPSF 1e-5f

// ---------------- f32x2 packed helpers ----------------
__device__ __forceinline__ ull pk2(float a, float b) {
    ull r; asm("mov.b64 %0, {%1, %2};" : "=l"(r) : "f"(a), "f"(b)); return r;
}
__device__ __forceinline__ void upk2(ull v, float& a, float& b) {
    asm("mov.b64 {%0, %1}, %2;" : "=f"(a), "=f"(b) : "l"(v));
}
__device__ __forceinline__ ull ffma2(ull a, ull b, ull c) {
    ull r; asm("fma.rn.f32x2 %0, %1, %2, %3;" : "=l"(r) : "l"(a), "l"(b), "l"(c)); return r;
}
__device__ __forceinline__ ull fmul2(ull a, ull b) {
    ull r; asm("mul.rn.f32x2 %0, %1, %2;" : "=l"(r) : "l"(a), "l"(b)); return r;
}
__device__ __forceinline__ ull fadd2(ull a, ull b) {
    ull r; asm("add.rn.f32x2 %0, %1, %2;" : "=l"(r) : "l"(a), "l"(b)); return r;
}

// ---------------- scratch (device globals; no allocation) ----------------
__device__ float g_u1[BB*CO*T1];     // pw1 output
__device__ float g_u2[BB*CO*T3];     // after depthwise conv (+bias)
__device__ float g_h [BB*HH*T3];     // running hidden state
__device__ float g_y [BB*HH*T3];     // s4 conv+gelu output
__device__ float g_st1[BB*2];        // GN1 sum/sumsq per batch
__device__ float g_st2[BB*2];        // GN2 sum/sumsq per batch
__device__ float g_Wm [HH*CO];       // fused enc∘pw2 matrix
__device__ float g_bv [HH];          // fused bias
__device__ float g_ar[NL*HH*NST];    // discrete a (real)
__device__ float g_ai[NL*HH*NST];
__device__ float g_cr[NL*HH*NST];    // 2*Cd (real)
__device__ float g_ci[NL*HH*NST];

// ---------------- tiny zero kernel (stats buffers) ----------------
__global__ void k_zero() {
    int i = threadIdx.x;
    if (i < BB*2) { g_st1[i] = 0.f; g_st2[i] = 0.f; }
}

// ---------------- all-layer S4D discretization constants ----------------
__global__ void k_s4c(const float* __restrict__ logdt, const float* __restrict__ logA,
                      const float* __restrict__ Aim,  const float* __restrict__ Cre,
                      const float* __restrict__ Cim) {
    int h = blockIdx.x, lay = blockIdx.y, n = threadIdx.x;
    int src = (lay*HH + h)*NST + n;
    float dt  = expf(logdt[lay*HH + h]);
    float Are = -expf(logA[src]);
    float Aii = Aim[src];
    float xre = Are * dt, xim = Aii * dt;
    float e = expf(xre);
    float are = e * cosf(xim);
    float aim = e * sinf(xim);
    float nre = are - 1.f, nim = aim;
    float den = Are*Are + Aii*Aii;
    float qre = (nre*Are + nim*Aii) / den;
    float qim = (nim*Are - nre*Aii) / den;
    float cre = Cre[src], cim = Cim[src];
    float cr = cre*qre - cim*qim;
    float ci = cre*qim + cim*qre;
    g_ar[src] = are; g_ai[src] = aim;
    g_cr[src] = 2.f*cr; g_ci[src] = 2.f*ci;
}

// ---------------- pw1 (64->32 pointwise, packed) + GN1 stats ----------------
__global__ __launch_bounds__(256) void k_pw1(const float* __restrict__ x,
                                             const float* __restrict__ w,
                                             const float* __restrict__ bias) {
    __shared__ float xs[C1][128];
    __shared__ float wst[C1][34];     // transposed [c][o], padded
    __shared__ float rs[8], rss[8];
    int b = blockIdx.y, t0 = blockIdx.x * 128;
    int tid = threadIdx.x;
    for (int i = tid; i < C1*128; i += 256) {
        int c = i >> 7, tt = i & 127;
        xs[c][tt] = x[(b*C1 + c)*T1 + t0 + tt];
    }
    for (int i = tid; i < CO*C1; i += 256) {
        int o = i >> 6, c = i & 63;
        wst[c][o] = w[i];
    }
    __syncthreads();
    int tt = tid & 127, half = tid >> 7;
    int ob0 = half * 16;
    ull acc[8];
#pragma unroll
    for (int p = 0; p < 8; p++) acc[p] = pk2(bias[ob0 + 2*p], bias[ob0 + 2*p + 1]);
    for (int c = 0; c < C1; c++) {
        float xv = xs[c][tt];
        ull X = pk2(xv, xv);
#pragma unroll
        for (int p = 0; p < 8; p++) {
            ull wv = *(const ull*)&wst[c][ob0 + 2*p];
            acc[p] = ffma2(wv, X, acc[p]);
        }
    }
    float s = 0.f, ss = 0.f;
#pragma unroll
    for (int p = 0; p < 8; p++) {
        float a0, a1; upk2(acc[p], a0, a1);
        int o = ob0 + 2*p;
        g_u1[(b*CO + o)*T1 + t0 + tt]     = a0;
        g_u1[(b*CO + o + 1)*T1 + t0 + tt] = a1;
        s += a0 + a1; ss += a0*a0 + a1*a1;
    }
#pragma unroll
    for (int off = 16; off; off >>= 1) {
        s  += __shfl_xor_sync(0xffffffffu, s,  off);
        ss += __shfl_xor_sync(0xffffffffu, ss, off);
    }
    int wid = tid >> 5;
    if ((tid & 31) == 0) { rs[wid] = s; rss[wid] = ss; }
    __syncthreads();
    if (tid == 0) {
        float a = 0.f, q = 0.f;
        for (int i = 0; i < 8; i++) { a += rs[i]; q += rss[i]; }
        atomicAdd(&g_st1[b*2],     a);
        atomicAdd(&g_st1[b*2 + 1], q);
    }
}

// ---- fused GN1-apply + GLU(time) + SiLU + depthwise conv (k=32) + GN2 stats ----
__global__ __launch_bounds__(256) void k_dwf(const float* __restrict__ w,
                                             const float* __restrict__ bias,
                                             const float* __restrict__ g1,
                                             const float* __restrict__ b1) {
    __shared__ float us[1024 + 36];
    __shared__ float wk[32];
    __shared__ float rs[8], rss[8];
    int t0 = blockIdx.x * 1024, c = blockIdx.y, b = blockIdx.z;
    int tid = threadIdx.x;
    if (tid < 32) wk[tid] = w[c*32 + tid];
    float n1 = (float)(CO * T1);
    float m1   = g_st1[b*2] / n1;
    float var1 = g_st1[b*2 + 1] / n1 - m1*m1;
    float rstd1 = rsqrtf(var1 + EPSF);
    float sc = rstd1 * g1[c], sh = b1[c] - m1 * sc;
    const float* base = g_u1 + (b*CO + c)*T1;
    for (int i = tid; i < 1060; i += 256) {
        int gi = t0 - 1 + i;
        float v = 0.f;
        if (gi >= 0 && gi < T2) {
            float ga = fmaf(base[gi],      sc, sh);
            float gb = fmaf(base[gi + T2], sc, sh);
            v = ga / (1.f + expf(-gb));   // GLU
            v = v / (1.f + expf(-v));     // SiLU
        }
        us[i] = v;
    }
    __syncthreads();
    int tt = tid * 4;
    // window of 36 values via 9 float4 reads
    float uw[36];
#pragma unroll
    for (int q = 0; q < 9; q++) {
        float4 v = *(const float4*)&us[tt + q*4];
        uw[q*4+0] = v.x; uw[q*4+1] = v.y; uw[q*4+2] = v.z; uw[q*4+3] = v.w;
    }
    float bc = bias[c];
    float a0 = bc, a1 = bc, a2 = bc, a3 = bc;
#pragma unroll
    for (int k = 0; k < 32; k++) {
        float wv = wk[k];
        a0 = fmaf(wv, uw[k],     a0);
        a1 = fmaf(wv, uw[k + 1], a1);
        a2 = fmaf(wv, uw[k + 2], a2);
        a3 = fmaf(wv, uw[k + 3], a3);
    }
    float s = 0.f, ss = 0.f;
    float* dst = g_u2 + (b*CO + c)*T3 + t0 + tt;
    float av[4] = {a0, a1, a2, a3};
#pragma unroll
    for (int r = 0; r < 4; r++) {
        int t = t0 + tt + r;
        if (t < T3) { dst[r] = av[r]; s += av[r]; ss += av[r]*av[r]; }
    }
#pragma unroll
    for (int off = 16; off; off >>= 1) {
        s  += __shfl_xor_sync(0xffffffffu, s,  off);
        ss += __shfl_xor_sync(0xffffffffu, ss, off);
    }
    int wid = tid >> 5;
    if ((tid & 31) == 0) { rs[wid] = s; rss[wid] = ss; }
    __syncthreads();
    if (tid == 0) {
        float a = 0.f, q = 0.f;
        for (int i = 0; i < 8; i++) { a += rs[i]; q += rss[i]; }
        atomicAdd(&g_st2[b*2],     a);
        atomicAdd(&g_st2[b*2 + 1], q);
    }
}

// ---------------- precompute fused (enc ∘ pw2) matrix ----------------
__global__ void k_prep(const float* __restrict__ pw2w, const float* __restrict__ pw2b,
                       const float* __restrict__ encw, const float* __restrict__ encb) {
    int tid = threadIdx.x;
    for (int i = tid; i < HH*CO; i += 256) {
        int d = i >> 5, cp = i & 31;
        float acc = 0.f;
        for (int c = 0; c < CO; c++)
            acc = fmaf(encw[c*HH + d], pw2w[c*CO + cp], acc);
        g_Wm[i] = acc;
    }
    if (tid < HH) {
        float acc = encb[tid];
        for (int c = 0; c < CO; c++)
            acc = fmaf(encw[c*HH + tid], pw2b[c], acc);
        g_bv[tid] = acc;
    }
}

// ---------------- GN2 apply + fused pw2∘enc -> h (packed) ----------------
__global__ __launch_bounds__(256) void k_enc(const float* __restrict__ g2,
                                             const float* __restrict__ b2) {
    __shared__ float un[CO][128];
    __shared__ float Wse[CO][66];    // transposed [c][d], padded
    int b = blockIdx.y, t0 = blockIdx.x * 128;
    int tid = threadIdx.x;
    float n = (float)(CO * T3);
    float m   = g_st2[b*2] / n;
    float var = g_st2[b*2 + 1] / n - m*m;
    float rstd = rsqrtf(var + EPSF);
    for (int i = tid; i < CO*128; i += 256) {
        int c = i >> 7, tt = i & 127;
        int t = t0 + tt;
        float v = (t < T3) ? g_u2[(b*CO + c)*T3 + t] : 0.f;
        un[c][tt] = (v - m) * rstd * g2[c] + b2[c];
    }
    for (int i = tid; i < HH*CO; i += 256) {
        int d = i >> 5, c = i & 31;
        Wse[c][d] = g_Wm[i];
    }
    __syncthreads();
    int tt = tid & 127, dg = tid >> 7;
    int d0 = dg * 32;
    ull acc[16];
#pragma unroll
    for (int p = 0; p < 16; p++) acc[p] = pk2(g_bv[d0 + 2*p], g_bv[d0 + 2*p + 1]);
    for (int c = 0; c < CO; c++) {
        float uv = un[c][tt];
        ull U = pk2(uv, uv);
#pragma unroll
        for (int p = 0; p < 16; p++) {
            ull wv = *(const ull*)&Wse[c][d0 + 2*p];
            acc[p] = ffma2(wv, U, acc[p]);
        }
    }
    int t = t0 + tt;
    if (t < T3) {
#pragma unroll
        for (int p = 0; p < 16; p++) {
            float a0, a1; upk2(acc[p], a0, a1);
            g_h[(b*HH + d0 + 2*p)*T3 + t]     = a0;
            g_h[(b*HH + d0 + 2*p + 1)*T3 + t] = a1;
        }
    }
}

// ---------------- S4D scan (packed f32x2): recurrence + D skip + GELU ----------------
__global__ __launch_bounds__(32) void k_scan(const float* __restrict__ D, int lay) {
    __shared__ ull ps[32*33];
    __shared__ float us[32];
    int lane = threadIdx.x;
    int gw = blockIdx.x;                 // 0..1023
    int b = gw >> 6, h = gw & 63;
    const float* ar = g_ar + (lay*HH + h)*NST;
    const float* ai = g_ai + (lay*HH + h)*NST;
    const float* cr = g_cr + (lay*HH + h)*NST;
    const float* ci = g_ci + (lay*HH + h)*NST;
    ull Ar  = pk2(ar[lane],  ar[lane+32]);
    ull Ai  = pk2(ai[lane],  ai[lane+32]);
    ull NAi = pk2(-ai[lane], -ai[lane+32]);
    ull Cr  = pk2(cr[lane],  cr[lane+32]);
    ull NCi = pk2(-ci[lane], -ci[lane+32]);
    float Dh = D[lay*HH + h];
    const float* uin = g_h + (b*HH + h)*T3;
    float* yo = g_y + (b*HH + h)*T3;
    ull Sr = 0ull, Si = 0ull;
    for (int c0 = 0; c0 < T3; c0 += 32) {
        int len = min(32, T3 - c0);
        float uval = (lane < len) ? uin[c0 + lane] : 0.f;
        us[lane] = uval;
        __syncwarp();
        if (len == 32) {
#pragma unroll
            for (int j = 0; j < 32; j++) {
                float u = us[j];
                ull U = pk2(u, u);
                ull T = ffma2(NAi, Si, U);
                ull M = fmul2(Ai, Sr);
                Sr = ffma2(Ar, Sr, T);
                Si = ffma2(Ar, Si, M);
                ull Q = fmul2(NCi, Si);
                Q = ffma2(Cr, Sr, Q);
                ps[lane*33 + j] = Q;
            }
        } else {
            for (int j = 0; j < len; j++) {
                float u = us[j];
                ull U = pk2(u, u);
                ull T = ffma2(NAi, Si, U);
                ull M = fmul2(Ai, Sr);
                Sr = ffma2(Ar, Sr, T);
                Si = ffma2(Ar, Si, M);
                ull Q = fmul2(NCi, Si);
                Q = ffma2(Cr, Sr, Q);
                ps[lane*33 + j] = Q;
            }
        }
        __syncwarp();
        if (lane < len) {
            ull acc = ps[lane];
#pragma unroll
            for (int k = 1; k < 32; k++) acc = fadd2(acc, ps[k*33 + lane]);
            float plo, phi; upk2(acc, plo, phi);
            float yv = fmaf(Dh, uval, plo + phi);
            yv = 0.5f * yv * (1.f + erff(yv * 0.70710678118f));   // exact GELU
            yo[c0 + lane] = yv;
        }
        __syncwarp();
    }
}

// ---- mixer: smem-tiled ow GEMM (packed) + GLU(ch) + residual + LN(ch) ----
__global__ __launch_bounds__(256) void k_mix(const float* __restrict__ ow,
                                             const float* __restrict__ ob,
                                             const float* __restrict__ lg,
                                             const float* __restrict__ lb, int lay) {
    __shared__ float Ws[64][130];      // [k][j], transposed, padded (33.3KB)
    __shared__ float ys[64][32];       // y tile; reused as z tile after GEMM
    __shared__ float rsum[8][32], rss2[8][32];
    __shared__ float mu[32], rstd[32];
    int b = blockIdx.y, t0 = blockIdx.x * 32;
    int tid = threadIdx.x;
    const float* owl = ow + lay*2*HH*HH;
    const float* obl = ob + lay*2*HH;
    // load W transposed: Ws[k][j] = owl[j][k]
    for (int i = tid; i < 2*HH*HH; i += 256) {
        int j = i >> 6, k = i & 63;
        Ws[k][j] = owl[i];
    }
    // load y tile
    for (int i = tid; i < HH*32; i += 256) {
        int ch = i >> 5, tt = i & 31;
        int t = t0 + tt;
        ys[ch][tt] = (t < T3) ? g_y[(b*HH + ch)*T3 + t] : 0.f;
    }
    __syncthreads();
    int chgrp = tid >> 3, tgrp = tid & 7;
    int ch0 = chgrp * 2, tsub = tgrp * 4;
    ull accA[4], accB[4];
    {
        ull ia = pk2(obl[ch0],      obl[ch0 + 1]);
        ull ib = pk2(obl[ch0 + 64], obl[ch0 + 65]);
#pragma unroll
        for (int t = 0; t < 4; t++) { accA[t] = ia; accB[t] = ib; }
    }
#pragma unroll 4
    for (int k = 0; k < 64; k++) {
        ull wa = *(const ull*)&Ws[k][ch0];
        ull wb = *(const ull*)&Ws[k][ch0 + 64];
        float4 yv = *(const float4*)&ys[k][tsub];
        ull y0 = pk2(yv.x, yv.x), y1 = pk2(yv.y, yv.y);
        ull y2 = pk2(yv.z, yv.z), y3 = pk2(yv.w, yv.w);
        accA[0] = ffma2(wa, y0, accA[0]);  accB[0] = ffma2(wb, y0, accB[0]);
        accA[1] = ffma2(wa, y1, accA[1]);  accB[1] = ffma2(wb, y1, accB[1]);
        accA[2] = ffma2(wa, y2, accA[2]);  accB[2] = ffma2(wb, y2, accB[2]);
        accA[3] = ffma2(wa, y3, accA[3]);  accB[3] = ffma2(wb, y3, accB[3]);
    }
    __syncthreads();                     // everyone done reading ys
    // epilogue: GLU + residual -> z (regs + smem reuse of ys)
    float zr0[4], zr1[4];
#pragma unroll
    for (int t = 0; t < 4; t++) {
        int tg = t0 + tsub + t;
        float oa0, oa1, og0, og1;
        upk2(accA[t], oa0, oa1);
        upk2(accB[t], og0, og1);
        float h0 = 0.f, h1 = 0.f;
        if (tg < T3) {
            h0 = g_h[(b*HH + ch0)*T3 + tg];
            h1 = g_h[(b*HH + ch0 + 1)*T3 + tg];
        }
        float z0 = oa0 / (1.f + expf(-og0)) + h0;
        float z1 = oa1 / (1.f + expf(-og1)) + h1;
        zr0[t] = z0; zr1[t] = z1;
        ys[ch0][tsub + t]     = z0;
        ys[ch0 + 1][tsub + t] = z1;
    }
    __syncthreads();
    // LN stats over 64 channels per t
    {
        int grp = tid >> 5, tsel = tid & 31;
        float s = 0.f, ss = 0.f;
#pragma unroll
        for (int q = 0; q < 8; q++) {
            float v = ys[grp*8 + q][tsel];
            s += v; ss += v*v;
        }
        rsum[grp][tsel] = s; rss2[grp][tsel] = ss;
    }
    __syncthreads();
    if (tid < 32) {
        float s = 0.f, ss = 0.f;
#pragma unroll
        for (int g = 0; g < 8; g++) { s += rsum[g][tid]; ss += rss2[g][tid]; }
        float m = s / 64.f;
        float var = ss / 64.f - m*m;
        mu[tid] = m; rstd[tid] = rsqrtf(var + EPSF);
    }
    __syncthreads();
    float lg0 = lg[lay*HH + ch0], lg1 = lg[lay*HH + ch0 + 1];
    float lb0 = lb[lay*HH + ch0], lb1 = lb[lay*HH + ch0 + 1];
#pragma unroll
    for (int t = 0; t < 4; t++) {
        int tg = t0 + tsub + t;
        if (tg < T3) {
            float m = mu[tsub + t], r = rstd[tsub + t];
            g_h[(b*HH + ch0)*T3 + tg]     = (zr0[t] - m) * r * lg0 + lb0;
            g_h[(b*HH + ch0 + 1)*T3 + tg] = (zr1[t] - m) * r * lg1 + lb1;
        }
    }
}

// ---------------- decoder: tiled packed GEMM (b,d,t)x(d,o) -> (b,t,o) ----------------
__global__ __launch_bounds__(256) void k_dec(const float* __restrict__ dw,
                                             const float* __restrict__ db,
                                             float* __restrict__ out) {
    __shared__ float wsd[HH][64];
    __shared__ float hsd[HH][64];
    int o0b = blockIdx.x * 64, t0 = blockIdx.y * 64, b = blockIdx.z;
    int tid = threadIdx.x;
    for (int i = tid; i < HH*64; i += 256) {
        int d = i >> 6, o = i & 63;
        wsd[d][o] = dw[d*DOUT + o0b + o];
    }
    for (int i = tid; i < HH*64; i += 256) {
        int d = i >> 6, tt = i & 63;
        int t = t0 + tt;
        hsd[d][tt] = (t < T3) ? g_h[(b*HH + d)*T3 + t] : 0.f;
    }
    __syncthreads();
    int ogrp = tid & 15, tgrp = tid >> 4;
    int o0 = ogrp * 4, tsub = tgrp * 4;
    ull accA[4], accB[4];
    {
        ull ia = pk2(db[o0b + o0],     db[o0b + o0 + 1]);
        ull ib = pk2(db[o0b + o0 + 2], db[o0b + o0 + 3]);
#pragma unroll
        for (int t = 0; t < 4; t++) { accA[t] = ia; accB[t] = ib; }
    }
#pragma unroll 4
    for (int k = 0; k < HH; k++) {
        ull wa = *(const ull*)&wsd[k][o0];
        ull wb = *(const ull*)&wsd[k][o0 + 2];
        float4 hv = *(const float4*)&hsd[k][tsub];
        ull h0 = pk2(hv.x, hv.x), h1 = pk2(hv.y, hv.y);
        ull h2 = pk2(hv.z, hv.z), h3 = pk2(hv.w, hv.w);
        accA[0] = ffma2(wa, h0, accA[0]);  accB[0] = ffma2(wb, h0, accB[0]);
        accA[1] = ffma2(wa, h1, accA[1]);  accB[1] = ffma2(wb, h1, accB[1]);
        accA[2] = ffma2(wa, h2, accA[2]);  accB[2] = ffma2(wb, h2, accB[2]);
        accA[3] = ffma2(wa, h3, accA[3]);  accB[3] = ffma2(wb, h3, accB[3]);
    }
#pragma unroll
    for (int t = 0; t < 4; t++) {
        int tg = t0 + tsub + t;
        if (tg < T3) {
            float4 o4;
            upk2(accA[t], o4.x, o4.y);
            upk2(accB[t], o4.z, o4.w);
            *(float4*)&out[((size_t)(b*T3 + tg))*DOUT + o0b + o0] = o4;
        }
    }
}

// ---------------- launcher ----------------
extern "C" void kernel_launch(void* const* d_in, const int* in_sizes, int n_in,
                              void* d_out, int out_size) {
    const float* x      = (const float*)d_in[0];
    const float* pw1w   = (const float*)d_in[1];
    const float* pw1b   = (const float*)d_in[2];
    const float* gn1g   = (const float*)d_in[3];
    const float* gn1b   = (const float*)d_in[4];
    const float* dww    = (const float*)d_in[5];
    const float* dwb    = (const float*)d_in[6];
    const float* gn2g   = (const float*)d_in[7];
    const float* gn2b   = (const float*)d_in[8];
    const float* pw2w   = (const float*)d_in[9];
    const float* pw2b   = (const float*)d_in[10];
    const float* encw   = (const float*)d_in[11];
    const float* encb   = (const float*)d_in[12];
    const float* logdt  = (const float*)d_in[13];
    const float* logA   = (const float*)d_in[14];
    const float* Aim    = (const float*)d_in[15];
    const float* Cre    = (const float*)d_in[16];
    const float* Cim    = (const float*)d_in[17];
    const float* s4D    = (const float*)d_in[18];
    const float* s4ow   = (const float*)d_in[19];
    const float* s4ob   = (const float*)d_in[20];
    const float* lng    = (const float*)d_in[21];
    const float* lnb    = (const float*)d_in[22];
    const float* decw   = (const float*)d_in[23];
    const float* decb   = (const float*)d_in[24];
    float* out = (float*)d_out;

    k_zero<<<1, 64>>>();
    k_s4c<<<dim3(HH, NL), NST>>>(logdt, logA, Aim, Cre, Cim);
    k_pw1<<<dim3(T1/128, BB), 256>>>(x, pw1w, pw1b);
    k_dwf<<<dim3(2, CO, BB), 256>>>(dww, dwb, gn1g, gn1b);
    k_prep<<<1, 256>>>(pw2w, pw2b, encw, encb);
    k_enc<<<dim3(16, BB), 256>>>(gn2g, gn2b);
    for (int l = 0; l < NL; l++) {
        k_scan<<<1024, 32>>>(s4D, l);
        k_mix<<<dim3(64, BB), 256>>>(s4ow, s4ob, lng, lnb, l);
    }
    k_dec<<<dim3(DOUT/64, 32, BB), 256>>>(decw, decb, out);
}

// round 7
// speedup vs baseline: 1.4196x; 1.2046x over previous
#include <cuda_runtime.h>
#include <math.h>

typedef unsigned long long ull;

// ---------------- problem constants ----------------
#define BB   16
#define C1   64
#define T1   4096
#define CO   32
#define T2   2048      // after GLU over time
#define T3   2019      // after depthwise conv k=32, pad(1,1)
#define HH   64        // d_model
#define NST  64        // S4 state size
#define NL   8
#define DOUT 640
#define EPSF 1e-5f
#define SEG  256       // scan segment length
#define NSEG 8         // ceil(T3/SEG)

// ---------------- f32x2 packed helpers ----------------
__device__ __forceinline__ ull pk2(float a, float b) {
    ull r; asm("mov.b64 %0, {%1, %2};" : "=l"(r) : "f"(a), "f"(b)); return r;
}
__device__ __forceinline__ void upk2(ull v, float& a, float& b) {
    asm("mov.b64 {%0, %1}, %2;" : "=f"(a), "=f"(b) : "l"(v));
}
__device__ __forceinline__ ull ffma2(ull a, ull b, ull c) {
    ull r; asm("fma.rn.f32x2 %0, %1, %2, %3;" : "=l"(r) : "l"(a), "l"(b), "l"(c)); return r;
}
__device__ __forceinline__ ull fmul2(ull a, ull b) {
    ull r; asm("mul.rn.f32x2 %0, %1, %2;" : "=l"(r) : "l"(a), "l"(b)); return r;
}
__device__ __forceinline__ ull fadd2(ull a, ull b) {
    ull r; asm("add.rn.f32x2 %0, %1, %2;" : "=l"(r) : "l"(a), "l"(b)); return r;
}

// ---------------- scratch (device globals; no allocation) ----------------
__device__ float g_u1[BB*CO*T1];     // pw1 output
__device__ float g_u2[BB*CO*T3];     // after depthwise conv (+bias)
__device__ float g_h [BB*HH*T3];     // running hidden state
__device__ float g_y [BB*HH*T3];     // s4 conv+gelu output
__device__ float g_st1[BB*2];        // GN1 sum/sumsq per batch
__device__ float g_st2[BB*2];        // GN2 sum/sumsq per batch
__device__ float g_Wm [HH*CO];       // fused enc∘pw2 matrix
__device__ float g_bv [HH];          // fused bias

// packed per-(lay,h,lane) S4 constants: lane holds states (lane, lane+32)
__device__ ull g_pAr [NL*HH*32];     // a real
__device__ ull g_pAi [NL*HH*32];     // a imag
__device__ ull g_pAin[NL*HH*32];     // -a imag
__device__ ull g_pCr [NL*HH*32];     // 2*Cd real
__device__ ull g_pCi [NL*HH*32];     // 2*Cd imag
__device__ ull g_pCin[NL*HH*32];     // -2*Cd imag
// a^(256k), k=0..6, packed
__device__ ull g_aPr [NL*HH*7*32];
__device__ ull g_aPi [NL*HH*7*32];
__device__ ull g_aPin[NL*HH*7*32];
// segment carries (re/im), [seg 0..6][bh][lane]
__device__ ull g_carR[7*BB*HH*32];
__device__ ull g_carI[7*BB*HH*32];

// ---------------- all-layer S4D constants + power tables (+stat zero) ----------------
__global__ void k_s4c(const float* __restrict__ logdt, const float* __restrict__ logA,
                      const float* __restrict__ Aim,  const float* __restrict__ Cre,
                      const float* __restrict__ Cim) {
    __shared__ float s_ar[64], s_ai[64], s_cr[64], s_ci[64];
    __shared__ float s_pr[7][64], s_pi[7][64];
    int h = blockIdx.x, lay = blockIdx.y, n = threadIdx.x;
    if (h == 0 && lay == 0 && n < BB*2) { g_st1[n] = 0.f; g_st2[n] = 0.f; }
    int src = (lay*HH + h)*NST + n;
    float dt  = expf(logdt[lay*HH + h]);
    float Are = -expf(logA[src]);
    float Aii = Aim[src];
    float e = expf(Are * dt);
    float are = e * cosf(Aii * dt);
    float aim = e * sinf(Aii * dt);
    float nre = are - 1.f, nim = aim;
    float den = Are*Are + Aii*Aii;
    float qre = (nre*Are + nim*Aii) / den;
    float qim = (nim*Are - nre*Aii) / den;
    float cre = Cre[src], cim = Cim[src];
    s_ar[n] = are; s_ai[n] = aim;
    s_cr[n] = 2.f*(cre*qre - cim*qim);
    s_ci[n] = 2.f*(cre*qim + cim*qre);
    // a^256 by 8 squarings
    float qr = are, qi = aim;
#pragma unroll
    for (int s = 0; s < 8; s++) {
        float nr = qr*qr - qi*qi, ni = 2.f*qr*qi;
        qr = nr; qi = ni;
    }
    float Pr = 1.f, Pi = 0.f;
    s_pr[0][n] = 1.f; s_pi[0][n] = 0.f;
#pragma unroll
    for (int k = 1; k < 7; k++) {
        float nr = Pr*qr - Pi*qi, ni = Pr*qi + Pi*qr;
        Pr = nr; Pi = ni;
        s_pr[k][n] = Pr; s_pi[k][n] = Pi;
    }
    __syncthreads();
    if (n < 32) {
        int base = (lay*HH + h)*32 + n;
        g_pAr [base] = pk2(s_ar[n],  s_ar[n+32]);
        g_pAi [base] = pk2(s_ai[n],  s_ai[n+32]);
        g_pAin[base] = pk2(-s_ai[n], -s_ai[n+32]);
        g_pCr [base] = pk2(s_cr[n],  s_cr[n+32]);
        g_pCi [base] = pk2(s_ci[n],  s_ci[n+32]);
        g_pCin[base] = pk2(-s_ci[n], -s_ci[n+32]);
#pragma unroll
        for (int k = 0; k < 7; k++) {
            int bp = ((lay*HH + h)*7 + k)*32 + n;
            g_aPr [bp] = pk2(s_pr[k][n],  s_pr[k][n+32]);
            g_aPi [bp] = pk2(s_pi[k][n],  s_pi[k][n+32]);
            g_aPin[bp] = pk2(-s_pi[k][n], -s_pi[k][n+32]);
        }
    }
}

// ---------------- pw1 (64->32 pointwise, packed) + GN1 stats ----------------
__global__ __launch_bounds__(256) void k_pw1(const float* __restrict__ x,
                                             const float* __restrict__ w,
                                             const float* __restrict__ bias) {
    __shared__ float xs[C1][128];
    __shared__ float wst[C1][34];
    __shared__ float rs[8], rss[8];
    int b = blockIdx.y, t0 = blockIdx.x * 128;
    int tid = threadIdx.x;
    for (int i = tid; i < C1*128; i += 256) {
        int c = i >> 7, tt = i & 127;
        xs[c][tt] = x[(b*C1 + c)*T1 + t0 + tt];
    }
    for (int i = tid; i < CO*C1; i += 256) {
        int o = i >> 6, c = i & 63;
        wst[c][o] = w[i];
    }
    __syncthreads();
    int tt = tid & 127, half = tid >> 7;
    int ob0 = half * 16;
    ull acc[8];
#pragma unroll
    for (int p = 0; p < 8; p++) acc[p] = pk2(bias[ob0 + 2*p], bias[ob0 + 2*p + 1]);
    for (int c = 0; c < C1; c++) {
        float xv = xs[c][tt];
        ull X = pk2(xv, xv);
#pragma unroll
        for (int p = 0; p < 8; p++) {
            ull wv = *(const ull*)&wst[c][ob0 + 2*p];
            acc[p] = ffma2(wv, X, acc[p]);
        }
    }
    float s = 0.f, ss = 0.f;
#pragma unroll
    for (int p = 0; p < 8; p++) {
        float a0, a1; upk2(acc[p], a0, a1);
        int o = ob0 + 2*p;
        g_u1[(b*CO + o)*T1 + t0 + tt]     = a0;
        g_u1[(b*CO + o + 1)*T1 + t0 + tt] = a1;
        s += a0 + a1; ss += a0*a0 + a1*a1;
    }
#pragma unroll
    for (int off = 16; off; off >>= 1) {
        s  += __shfl_xor_sync(0xffffffffu, s,  off);
        ss += __shfl_xor_sync(0xffffffffu, ss, off);
    }
    int wid = tid >> 5;
    if ((tid & 31) == 0) { rs[wid] = s; rss[wid] = ss; }
    __syncthreads();
    if (tid == 0) {
        float a = 0.f, q = 0.f;
        for (int i = 0; i < 8; i++) { a += rs[i]; q += rss[i]; }
        atomicAdd(&g_st1[b*2],     a);
        atomicAdd(&g_st1[b*2 + 1], q);
    }
}

// ---- fused GN1-apply + GLU(time) + SiLU + depthwise conv (k=32) + GN2 stats ----
__global__ __launch_bounds__(256) void k_dwf(const float* __restrict__ w,
                                             const float* __restrict__ bias,
                                             const float* __restrict__ g1,
                                             const float* __restrict__ b1) {
    __shared__ float us[1024 + 36];
    __shared__ float wk[32];
    __shared__ float rs[8], rss[8];
    int t0 = blockIdx.x * 1024, c = blockIdx.y, b = blockIdx.z;
    int tid = threadIdx.x;
    if (tid < 32) wk[tid] = w[c*32 + tid];
    float n1 = (float)(CO * T1);
    float m1   = g_st1[b*2] / n1;
    float var1 = g_st1[b*2 + 1] / n1 - m1*m1;
    float rstd1 = rsqrtf(var1 + EPSF);
    float sc = rstd1 * g1[c], sh = b1[c] - m1 * sc;
    const float* base = g_u1 + (b*CO + c)*T1;
    for (int i = tid; i < 1060; i += 256) {
        int gi = t0 - 1 + i;
        float v = 0.f;
        if (gi >= 0 && gi < T2) {
            float ga = fmaf(base[gi],      sc, sh);
            float gb = fmaf(base[gi + T2], sc, sh);
            v = ga / (1.f + expf(-gb));
            v = v / (1.f + expf(-v));
        }
        us[i] = v;
    }
    __syncthreads();
    int tt = tid * 4;
    float uw[36];
#pragma unroll
    for (int q = 0; q < 9; q++) {
        float4 v = *(const float4*)&us[tt + q*4];
        uw[q*4+0] = v.x; uw[q*4+1] = v.y; uw[q*4+2] = v.z; uw[q*4+3] = v.w;
    }
    float bc = bias[c];
    float a0 = bc, a1 = bc, a2 = bc, a3 = bc;
#pragma unroll
    for (int k = 0; k < 32; k++) {
        float wv = wk[k];
        a0 = fmaf(wv, uw[k],     a0);
        a1 = fmaf(wv, uw[k + 1], a1);
        a2 = fmaf(wv, uw[k + 2], a2);
        a3 = fmaf(wv, uw[k + 3], a3);
    }
    float s = 0.f, ss = 0.f;
    float* dst = g_u2 + (b*CO + c)*T3 + t0 + tt;
    float av[4] = {a0, a1, a2, a3};
#pragma unroll
    for (int r = 0; r < 4; r++) {
        int t = t0 + tt + r;
        if (t < T3) { dst[r] = av[r]; s += av[r]; ss += av[r]*av[r]; }
    }
#pragma unroll
    for (int off = 16; off; off >>= 1) {
        s  += __shfl_xor_sync(0xffffffffu, s,  off);
        ss += __shfl_xor_sync(0xffffffffu, ss, off);
    }
    int wid = tid >> 5;
    if ((tid & 31) == 0) { rs[wid] = s; rss[wid] = ss; }
    __syncthreads();
    if (tid == 0) {
        float a = 0.f, q = 0.f;
        for (int i = 0; i < 8; i++) { a += rs[i]; q += rss[i]; }
        atomicAdd(&g_st2[b*2],     a);
        atomicAdd(&g_st2[b*2 + 1], q);
    }
}

// ---------------- precompute fused (enc ∘ pw2) matrix ----------------
__global__ void k_prep(const float* __restrict__ pw2w, const float* __restrict__ pw2b,
                       const float* __restrict__ encw, const float* __restrict__ encb) {
    int tid = threadIdx.x;
    for (int i = tid; i < HH*CO; i += 256) {
        int d = i >> 5, cp = i & 31;
        float acc = 0.f;
        for (int c = 0; c < CO; c++)
            acc = fmaf(encw[c*HH + d], pw2w[c*CO + cp], acc);
        g_Wm[i] = acc;
    }
    if (tid < HH) {
        float acc = encb[tid];
        for (int c = 0; c < CO; c++)
            acc = fmaf(encw[c*HH + tid], pw2b[c], acc);
        g_bv[tid] = acc;
    }
}

// ---------------- GN2 apply + fused pw2∘enc -> h (packed) ----------------
__global__ __launch_bounds__(256) void k_enc(const float* __restrict__ g2,
                                             const float* __restrict__ b2) {
    __shared__ float un[CO][128];
    __shared__ float Wse[CO][66];
    int b = blockIdx.y, t0 = blockIdx.x * 128;
    int tid = threadIdx.x;
    float n = (float)(CO * T3);
    float m   = g_st2[b*2] / n;
    float var = g_st2[b*2 + 1] / n - m*m;
    float rstd = rsqrtf(var + EPSF);
    for (int i = tid; i < CO*128; i += 256) {
        int c = i >> 7, tt = i & 127;
        int t = t0 + tt;
        float v = (t < T3) ? g_u2[(b*CO + c)*T3 + t] : 0.f;
        un[c][tt] = (v - m) * rstd * g2[c] + b2[c];
    }
    for (int i = tid; i < HH*CO; i += 256) {
        int d = i >> 5, c = i & 31;
        Wse[c][d] = g_Wm[i];
    }
    __syncthreads();
    int tt = tid & 127, dg = tid >> 7;
    int d0 = dg * 32;
    ull acc[16];
#pragma unroll
    for (int p = 0; p < 16; p++) acc[p] = pk2(g_bv[d0 + 2*p], g_bv[d0 + 2*p + 1]);
    for (int c = 0; c < CO; c++) {
        float uv = un[c][tt];
        ull U = pk2(uv, uv);
#pragma unroll
        for (int p = 0; p < 16; p++) {
            ull wv = *(const ull*)&Wse[c][d0 + 2*p];
            acc[p] = ffma2(wv, U, acc[p]);
        }
    }
    int t = t0 + tt;
    if (t < T3) {
#pragma unroll
        for (int p = 0; p < 16; p++) {
            float a0, a1; upk2(acc[p], a0, a1);
            g_h[(b*HH + d0 + 2*p)*T3 + t]     = a0;
            g_h[(b*HH + d0 + 2*p + 1)*T3 + t] = a1;
        }
    }
}

// ---------------- scan pass A: per-segment carries (segments 0..6) ----------------
__global__ __launch_bounds__(128) void k_scA(int lay) {
    __shared__ ull us2[4][32];
    int lane = threadIdx.x & 31, wl = threadIdx.x >> 5;
    int wg = blockIdx.x * 4 + wl;            // 0..7167
    int bh = wg & 1023, p = wg >> 10;        // p in 0..6
    int b = bh >> 6, h = bh & 63;
    int cbase = (lay*HH + h)*32 + lane;
    ull Ar  = g_pAr [cbase];
    ull Ai  = g_pAi [cbase];
    ull NAi = g_pAin[cbase];
    const float* uin = g_h + (b*HH + h)*T3 + p*SEG;
    ull* usw = us2[wl];
    ull Sr = 0ull, Si = 0ull;
    for (int c0 = 0; c0 < SEG; c0 += 32) {
        float u = uin[c0 + lane];
        usw[lane] = pk2(u, u);
        __syncwarp();
#pragma unroll
        for (int j = 0; j < 32; j++) {
            ull U = usw[j];
            ull t = ffma2(NAi, Si, U);
            ull m = fmul2(Ai, Sr);
            Sr = ffma2(Ar, Sr, t);
            Si = ffma2(Ar, Si, m);
        }
        __syncwarp();
    }
    int ci = (p*BB*HH + bh)*32 + lane;
    g_carR[ci] = Sr;
    g_carI[ci] = Si;
}

// ---------------- scan pass C: combine carries, z-form output scan ----------------
__global__ __launch_bounds__(128) void k_scC(const float* __restrict__ D, int lay) {
    __shared__ ull ps[4][32*33];
    __shared__ ull us2[4][32];
    int lane = threadIdx.x & 31, wl = threadIdx.x >> 5;
    int wg = blockIdx.x * 4 + wl;            // 0..8191
    int bh = wg & 1023, p = wg >> 10;        // p in 0..7
    int b = bh >> 6, h = bh & 63;
    int cbase = (lay*HH + h)*32 + lane;
    ull Ar  = g_pAr [cbase];
    ull Ai  = g_pAi [cbase];
    ull NAi = g_pAin[cbase];
    ull CcR = g_pCr [cbase];
    ull CcI = g_pCi [cbase];
    ull CcIn= g_pCin[cbase];
    float Dh = D[lay*HH + h];
    // reconstruct segment-start state S_p from predecessors' carries
    ull Sr = 0ull, Si = 0ull;
    for (int q = 0; q < p; q++) {
        int k = p - 1 - q;
        int bp = ((lay*HH + h)*7 + k)*32 + lane;
        ull aPr  = g_aPr [bp];
        ull aPi  = g_aPi [bp];
        ull aPin = g_aPin[bp];
        int ci = (q*BB*HH + bh)*32 + lane;
        ull CqR = g_carR[ci], CqI = g_carI[ci];
        Sr = ffma2(aPr,  CqR, Sr);
        Sr = ffma2(aPin, CqI, Sr);
        Si = ffma2(aPr,  CqI, Si);
        Si = ffma2(aPi,  CqR, Si);
    }
    // z = Cc ⊙ S
    ull zr = ffma2(CcR, Sr, fmul2(CcIn, Si));
    ull zi = ffma2(CcR, Si, fmul2(CcI,  Sr));
    int t0 = p * SEG;
    int len = min(SEG, T3 - t0);
    const float* uin = g_h + (b*HH + h)*T3 + t0;
    float* yo = g_y + (b*HH + h)*T3 + t0;
    ull* psw = ps[wl];
    ull* usw = us2[wl];
    for (int c0 = 0; c0 < len; c0 += 32) {
        int lc = min(32, len - c0);
        float uval = 0.f;
        if (lane < lc) {
            uval = uin[c0 + lane];
            usw[lane] = pk2(uval, uval);
        }
        __syncwarp();
        if (lc == 32) {
#pragma unroll
            for (int j = 0; j < 32; j++) {
                ull U = usw[j];
                ull t1 = ffma2(NAi, zi, fmul2(CcR, U));
                ull t3 = ffma2(Ai,  zr, fmul2(CcI, U));
                zr = ffma2(Ar, zr, t1);
                zi = ffma2(Ar, zi, t3);
                psw[lane*33 + j] = zr;
            }
        } else {
            for (int j = 0; j < lc; j++) {
                ull U = usw[j];
                ull t1 = ffma2(NAi, zi, fmul2(CcR, U));
                ull t3 = ffma2(Ai,  zr, fmul2(CcI, U));
                zr = ffma2(Ar, zr, t1);
                zi = ffma2(Ar, zi, t3);
                psw[lane*33 + j] = zr;
            }
        }
        __syncwarp();
        if (lane < lc) {
            ull acc0 = psw[lane];
            ull acc1 = psw[33 + lane];
#pragma unroll
            for (int k = 2; k < 32; k += 2) {
                acc0 = fadd2(acc0, psw[k*33 + lane]);
                acc1 = fadd2(acc1, psw[(k+1)*33 + lane]);
            }
            ull acc = fadd2(acc0, acc1);
            float plo, phi; upk2(acc, plo, phi);
            float yv = fmaf(Dh, uval, plo + phi);
            yv = 0.5f * yv * (1.f + erff(yv * 0.70710678118f));
            yo[c0 + lane] = yv;
        }
        __syncwarp();
    }
}

// ---- mixer: smem-tiled ow GEMM (packed) + GLU(ch) + residual + LN(ch) ----
__global__ __launch_bounds__(256) void k_mix(const float* __restrict__ ow,
                                             const float* __restrict__ ob,
                                             const float* __restrict__ lg,
                                             const float* __restrict__ lb, int lay) {
    __shared__ float Ws[64][130];
    __shared__ float ys[64][32];
    __shared__ float rsum[8][32], rss2[8][32];
    __shared__ float mu[32], rstd[32];
    int b = blockIdx.y, t0 = blockIdx.x * 32;
    int tid = threadIdx.x;
    const float* owl = ow + lay*2*HH*HH;
    const float* obl = ob + lay*2*HH;
    for (int i = tid; i < 2*HH*HH; i += 256) {
        int j = i >> 6, k = i & 63;
        Ws[k][j] = owl[i];
    }
    for (int i = tid; i < HH*32; i += 256) {
        int ch = i >> 5, tt = i & 31;
        int t = t0 + tt;
        ys[ch][tt] = (t < T3) ? g_y[(b*HH + ch)*T3 + t] : 0.f;
    }
    __syncthreads();
    int chgrp = tid >> 3, tgrp = tid & 7;
    int ch0 = chgrp * 2, tsub = tgrp * 4;
    ull accA[4], accB[4];
    {
        ull ia = pk2(obl[ch0],      obl[ch0 + 1]);
        ull ib = pk2(obl[ch0 + 64], obl[ch0 + 65]);
#pragma unroll
        for (int t = 0; t < 4; t++) { accA[t] = ia; accB[t] = ib; }
    }
#pragma unroll 4
    for (int k = 0; k < 64; k++) {
        ull wa = *(const ull*)&Ws[k][ch0];
        ull wb = *(const ull*)&Ws[k][ch0 + 64];
        float4 yv = *(const float4*)&ys[k][tsub];
        ull y0 = pk2(yv.x, yv.x), y1 = pk2(yv.y, yv.y);
        ull y2 = pk2(yv.z, yv.z), y3 = pk2(yv.w, yv.w);
        accA[0] = ffma2(wa, y0, accA[0]);  accB[0] = ffma2(wb, y0, accB[0]);
        accA[1] = ffma2(wa, y1, accA[1]);  accB[1] = ffma2(wb, y1, accB[1]);
        accA[2] = ffma2(wa, y2, accA[2]);  accB[2] = ffma2(wb, y2, accB[2]);
        accA[3] = ffma2(wa, y3, accA[3]);  accB[3] = ffma2(wb, y3, accB[3]);
    }
    __syncthreads();
    float zr0[4], zr1[4];
#pragma unroll
    for (int t = 0; t < 4; t++) {
        int tg = t0 + tsub + t;
        float oa0, oa1, og0, og1;
        upk2(accA[t], oa0, oa1);
        upk2(accB[t], og0, og1);
        float h0 = 0.f, h1 = 0.f;
        if (tg < T3) {
            h0 = g_h[(b*HH + ch0)*T3 + tg];
            h1 = g_h[(b*HH + ch0 + 1)*T3 + tg];
        }
        float z0 = oa0 / (1.f + expf(-og0)) + h0;
        float z1 = oa1 / (1.f + expf(-og1)) + h1;
        zr0[t] = z0; zr1[t] = z1;
        ys[ch0][tsub + t]     = z0;
        ys[ch0 + 1][tsub + t] = z1;
    }
    __syncthreads();
    {
        int grp = tid >> 5, tsel = tid & 31;
        float s = 0.f, ss = 0.f;
#pragma unroll
        for (int q = 0; q < 8; q++) {
            float v = ys[grp*8 + q][tsel];
            s += v; ss += v*v;
        }
        rsum[grp][tsel] = s; rss2[grp][tsel] = ss;
    }
    __syncthreads();
    if (tid < 32) {
        float s = 0.f, ss = 0.f;
#pragma unroll
        for (int g = 0; g < 8; g++) { s += rsum[g][tid]; ss += rss2[g][tid]; }
        float m = s / 64.f;
        float var = ss / 64.f - m*m;
        mu[tid] = m; rstd[tid] = rsqrtf(var + EPSF);
    }
    __syncthreads();
    float lg0 = lg[lay*HH + ch0], lg1 = lg[lay*HH + ch0 + 1];
    float lb0 = lb[lay*HH + ch0], lb1 = lb[lay*HH + ch0 + 1];
#pragma unroll
    for (int t = 0; t < 4; t++) {
        int tg = t0 + tsub + t;
        if (tg < T3) {
            float m = mu[tsub + t], r = rstd[tsub + t];
            g_h[(b*HH + ch0)*T3 + tg]     = (zr0[t] - m) * r * lg0 + lb0;
            g_h[(b*HH + ch0 + 1)*T3 + tg] = (zr1[t] - m) * r * lg1 + lb1;
        }
    }
}

// ---------------- decoder: tiled packed GEMM (b,d,t)x(d,o) -> (b,t,o) ----------------
__global__ __launch_bounds__(256) void k_dec(const float* __restrict__ dw,
                                             const float* __restrict__ db,
                                             float* __restrict__ out) {
    __shared__ float wsd[HH][64];
    __shared__ float hsd[HH][64];
    int o0b = blockIdx.x * 64, t0 = blockIdx.y * 64, b = blockIdx.z;
    int tid = threadIdx.x;
    for (int i = tid; i < HH*64; i += 256) {
        int d = i >> 6, o = i & 63;
        wsd[d][o] = dw[d*DOUT + o0b + o];
    }
    for (int i = tid; i < HH*64; i += 256) {
        int d = i >> 6, tt = i & 63;
        int t = t0 + tt;
        hsd[d][tt] = (t < T3) ? g_h[(b*HH + d)*T3 + t] : 0.f;
    }
    __syncthreads();
    int ogrp = tid & 15, tgrp = tid >> 4;
    int o0 = ogrp * 4, tsub = tgrp * 4;
    ull accA[4], accB[4];
    {
        ull ia = pk2(db[o0b + o0],     db[o0b + o0 + 1]);
        ull ib = pk2(db[o0b + o0 + 2], db[o0b + o0 + 3]);
#pragma unroll
        for (int t = 0; t < 4; t++) { accA[t] = ia; accB[t] = ib; }
    }
#pragma unroll 4
    for (int k = 0; k < HH; k++) {
        ull wa = *(const ull*)&wsd[k][o0];
        ull wb = *(const ull*)&wsd[k][o0 + 2];
        float4 hv = *(const float4*)&hsd[k][tsub];
        ull h0 = pk2(hv.x, hv.x), h1 = pk2(hv.y, hv.y);
        ull h2 = pk2(hv.z, hv.z), h3 = pk2(hv.w, hv.w);
        accA[0] = ffma2(wa, h0, accA[0]);  accB[0] = ffma2(wb, h0, accB[0]);
        accA[1] = ffma2(wa, h1, accA[1]);  accB[1] = ffma2(wb, h1, accB[1]);
        accA[2] = ffma2(wa, h2, accA[2]);  accB[2] = ffma2(wb, h2, accB[2]);
        accA[3] = ffma2(wa, h3, accA[3]);  accB[3] = ffma2(wb, h3, accB[3]);
    }
#pragma unroll
    for (int t = 0; t < 4; t++) {
        int tg = t0 + tsub + t;
        if (tg < T3) {
            float4 o4;
            upk2(accA[t], o4.x, o4.y);
            upk2(accB[t], o4.z, o4.w);
            *(float4*)&out[((size_t)(b*T3 + tg))*DOUT + o0b + o0] = o4;
        }
    }
}

// ---------------- launcher ----------------
extern "C" void kernel_launch(void* const* d_in, const int* in_sizes, int n_in,
                              void* d_out, int out_size) {
    const float* x      = (const float*)d_in[0];
    const float* pw1w   = (const float*)d_in[1];
    const float* pw1b   = (const float*)d_in[2];
    const float* gn1g   = (const float*)d_in[3];
    const float* gn1b   = (const float*)d_in[4];
    const float* dww    = (const float*)d_in[5];
    const float* dwb    = (const float*)d_in[6];
    const float* gn2g   = (const float*)d_in[7];
    const float* gn2b   = (const float*)d_in[8];
    const float* pw2w   = (const float*)d_in[9];
    const float* pw2b   = (const float*)d_in[10];
    const float* encw   = (const float*)d_in[11];
    const float* encb   = (const float*)d_in[12];
    const float* logdt  = (const float*)d_in[13];
    const float* logA   = (const float*)d_in[14];
    const float* Aim    = (const float*)d_in[15];
    const float* Cre    = (const float*)d_in[16];
    const float* Cim    = (const float*)d_in[17];
    const float* s4D    = (const float*)d_in[18];
    const float* s4ow   = (const float*)d_in[19];
    const float* s4ob   = (const float*)d_in[20];
    const float* lng    = (const float*)d_in[21];
    const float* lnb    = (const float*)d_in[22];
    const float* decw   = (const float*)d_in[23];
    const float* decb   = (const float*)d_in[24];
    float* out = (float*)d_out;

    k_s4c<<<dim3(HH, NL), 64>>>(logdt, logA, Aim, Cre, Cim);
    k_pw1<<<dim3(T1/128, BB), 256>>>(x, pw1w, pw1b);
    k_dwf<<<dim3(2, CO, BB), 256>>>(dww, dwb, gn1g, gn1b);
    k_prep<<<1, 256>>>(pw2w, pw2b, encw, encb);
    k_enc<<<dim3(16, BB), 256>>>(gn2g, gn2b);
    for (int l = 0; l < NL; l++) {
        k_scA<<<(BB*HH*7)/4, 128>>>(l);
        k_scC<<<(BB*HH*NSEG)/4, 128>>>(s4D, l);
        k_mix<<<dim3(64, BB), 256>>>(s4ow, s4ob, lng, lnb, l);
    }
    k_dec<<<dim3(DOUT/64, 32, BB), 256>>>(decw, decb, out);
}

// round 8
// speedup vs baseline: 1.5448x; 1.0882x over previous
#include <cuda_runtime.h>
#include <math.h>

typedef unsigned long long ull;

// ---------------- problem constants ----------------
#define BB   16
#define C1   64
#define T1   4096
#define CO   32
#define T2   2048      // after GLU over time
#define T3   2019      // after depthwise conv k=32, pad(1,1)
#define HH   64        // d_model
#define NST  64        // S4 state size
#define NL   8
#define DOUT 640
#define EPSF 1e-5f
#define SEG  256       // scan segment length
#define NSEG 8         // ceil(T3/SEG)

// ---------------- f32x2 packed helpers ----------------
__device__ __forceinline__ ull pk2(float a, float b) {
    ull r; asm("mov.b64 %0, {%1, %2};" : "=l"(r) : "f"(a), "f"(b)); return r;
}
__device__ __forceinline__ void upk2(ull v, float& a, float& b) {
    asm("mov.b64 {%0, %1}, %2;" : "=f"(a), "=f"(b) : "l"(v));
}
__device__ __forceinline__ ull ffma2(ull a, ull b, ull c) {
    ull r; asm("fma.rn.f32x2 %0, %1, %2, %3;" : "=l"(r) : "l"(a), "l"(b), "l"(c)); return r;
}
__device__ __forceinline__ ull fmul2(ull a, ull b) {
    ull r; asm("mul.rn.f32x2 %0, %1, %2;" : "=l"(r) : "l"(a), "l"(b)); return r;
}
__device__ __forceinline__ ull fadd2(ull a, ull b) {
    ull r; asm("add.rn.f32x2 %0, %1, %2;" : "=l"(r) : "l"(a), "l"(b)); return r;
}

// ---------------- scratch (device globals; no allocation) ----------------
__device__ float g_u1[BB*CO*T1];     // pw1 output
__device__ float g_u2[BB*CO*T3];     // after depthwise conv (+bias)
__device__ float g_h [BB*HH*T3];     // running hidden state
__device__ float g_y [BB*HH*T3];     // s4 conv+gelu output
__device__ float g_st1[BB*2];        // GN1 sum/sumsq per batch
__device__ float g_st2[BB*2];        // GN2 sum/sumsq per batch
__device__ float g_Wm [HH*CO];       // fused enc∘pw2 matrix
__device__ float g_bv [HH];          // fused bias

// packed per-(lay,h,lane) S4 constants: lane holds states (lane, lane+32)
__device__ ull g_pAr [NL*HH*32];     // a real
__device__ ull g_pAi [NL*HH*32];     // a imag
__device__ ull g_pAin[NL*HH*32];     // -a imag
__device__ ull g_pCr [NL*HH*32];     // 2*Cd real
__device__ ull g_pCi [NL*HH*32];     // 2*Cd imag
__device__ ull g_pCin[NL*HH*32];     // -2*Cd imag
// a^(256k), k=0..6, packed
__device__ ull g_aPr [NL*HH*7*32];
__device__ ull g_aPi [NL*HH*7*32];
__device__ ull g_aPin[NL*HH*7*32];
// segment carries (re/im), [seg 0..6][bh][lane]
__device__ ull g_carR[7*BB*HH*32];
__device__ ull g_carI[7*BB*HH*32];

// ---------------- all-layer S4D constants + power tables (+stat zero) ----------------
__global__ void k_s4c(const float* __restrict__ logdt, const float* __restrict__ logA,
                      const float* __restrict__ Aim,  const float* __restrict__ Cre,
                      const float* __restrict__ Cim) {
    __shared__ float s_ar[64], s_ai[64], s_cr[64], s_ci[64];
    __shared__ float s_pr[7][64], s_pi[7][64];
    int h = blockIdx.x, lay = blockIdx.y, n = threadIdx.x;
    if (h == 0 && lay == 0 && n < BB*2) { g_st1[n] = 0.f; g_st2[n] = 0.f; }
    int src = (lay*HH + h)*NST + n;
    float dt  = expf(logdt[lay*HH + h]);
    float Are = -expf(logA[src]);
    float Aii = Aim[src];
    float e = expf(Are * dt);
    float are = e * cosf(Aii * dt);
    float aim = e * sinf(Aii * dt);
    float nre = are - 1.f, nim = aim;
    float den = Are*Are + Aii*Aii;
    float qre = (nre*Are + nim*Aii) / den;
    float qim = (nim*Are - nre*Aii) / den;
    float cre = Cre[src], cim = Cim[src];
    s_ar[n] = are; s_ai[n] = aim;
    s_cr[n] = 2.f*(cre*qre - cim*qim);
    s_ci[n] = 2.f*(cre*qim + cim*qre);
    float qr = are, qi = aim;
#pragma unroll
    for (int s = 0; s < 8; s++) {
        float nr = qr*qr - qi*qi, ni = 2.f*qr*qi;
        qr = nr; qi = ni;
    }
    float Pr = 1.f, Pi = 0.f;
    s_pr[0][n] = 1.f; s_pi[0][n] = 0.f;
#pragma unroll
    for (int k = 1; k < 7; k++) {
        float nr = Pr*qr - Pi*qi, ni = Pr*qi + Pi*qr;
        Pr = nr; Pi = ni;
        s_pr[k][n] = Pr; s_pi[k][n] = Pi;
    }
    __syncthreads();
    if (n < 32) {
        int base = (lay*HH + h)*32 + n;
        g_pAr [base] = pk2(s_ar[n],  s_ar[n+32]);
        g_pAi [base] = pk2(s_ai[n],  s_ai[n+32]);
        g_pAin[base] = pk2(-s_ai[n], -s_ai[n+32]);
        g_pCr [base] = pk2(s_cr[n],  s_cr[n+32]);
        g_pCi [base] = pk2(s_ci[n],  s_ci[n+32]);
        g_pCin[base] = pk2(-s_ci[n], -s_ci[n+32]);
#pragma unroll
        for (int k = 0; k < 7; k++) {
            int bp = ((lay*HH + h)*7 + k)*32 + n;
            g_aPr [bp] = pk2(s_pr[k][n],  s_pr[k][n+32]);
            g_aPi [bp] = pk2(s_pi[k][n],  s_pi[k][n+32]);
            g_aPin[bp] = pk2(-s_pi[k][n], -s_pi[k][n+32]);
        }
    }
}

// ---------------- pw1 (64->32 pointwise, packed) + GN1 stats ----------------
__global__ __launch_bounds__(256) void k_pw1(const float* __restrict__ x,
                                             const float* __restrict__ w,
                                             const float* __restrict__ bias) {
    __shared__ float xs[C1][128];
    __shared__ float wst[C1][34];
    __shared__ float rs[8], rss[8];
    int b = blockIdx.y, t0 = blockIdx.x * 128;
    int tid = threadIdx.x;
    for (int i = tid; i < C1*128; i += 256) {
        int c = i >> 7, tt = i & 127;
        xs[c][tt] = x[(b*C1 + c)*T1 + t0 + tt];
    }
    for (int i = tid; i < CO*C1; i += 256) {
        int o = i >> 6, c = i & 63;
        wst[c][o] = w[i];
    }
    __syncthreads();
    int tt = tid & 127, half = tid >> 7;
    int ob0 = half * 16;
    ull acc[8];
#pragma unroll
    for (int p = 0; p < 8; p++) acc[p] = pk2(bias[ob0 + 2*p], bias[ob0 + 2*p + 1]);
    for (int c = 0; c < C1; c++) {
        float xv = xs[c][tt];
        ull X = pk2(xv, xv);
#pragma unroll
        for (int p = 0; p < 8; p++) {
            ull wv = *(const ull*)&wst[c][ob0 + 2*p];
            acc[p] = ffma2(wv, X, acc[p]);
        }
    }
    float s = 0.f, ss = 0.f;
#pragma unroll
    for (int p = 0; p < 8; p++) {
        float a0, a1; upk2(acc[p], a0, a1);
        int o = ob0 + 2*p;
        g_u1[(b*CO + o)*T1 + t0 + tt]     = a0;
        g_u1[(b*CO + o + 1)*T1 + t0 + tt] = a1;
        s += a0 + a1; ss += a0*a0 + a1*a1;
    }
#pragma unroll
    for (int off = 16; off; off >>= 1) {
        s  += __shfl_xor_sync(0xffffffffu, s,  off);
        ss += __shfl_xor_sync(0xffffffffu, ss, off);
    }
    int wid = tid >> 5;
    if ((tid & 31) == 0) { rs[wid] = s; rss[wid] = ss; }
    __syncthreads();
    if (tid == 0) {
        float a = 0.f, q = 0.f;
        for (int i = 0; i < 8; i++) { a += rs[i]; q += rss[i]; }
        atomicAdd(&g_st1[b*2],     a);
        atomicAdd(&g_st1[b*2 + 1], q);
    }
}

// ---- fused GN1-apply + GLU(time) + SiLU + depthwise conv (k=32) + GN2 stats ----
__global__ __launch_bounds__(256) void k_dwf(const float* __restrict__ w,
                                             const float* __restrict__ bias,
                                             const float* __restrict__ g1,
                                             const float* __restrict__ b1) {
    __shared__ float us[1024 + 36];
    __shared__ float wk[32];
    __shared__ float rs[8], rss[8];
    int t0 = blockIdx.x * 1024, c = blockIdx.y, b = blockIdx.z;
    int tid = threadIdx.x;
    if (tid < 32) wk[tid] = w[c*32 + tid];
    float n1 = (float)(CO * T1);
    float m1   = g_st1[b*2] / n1;
    float var1 = g_st1[b*2 + 1] / n1 - m1*m1;
    float rstd1 = rsqrtf(var1 + EPSF);
    float sc = rstd1 * g1[c], sh = b1[c] - m1 * sc;
    const float* base = g_u1 + (b*CO + c)*T1;
    for (int i = tid; i < 1060; i += 256) {
        int gi = t0 - 1 + i;
        float v = 0.f;
        if (gi >= 0 && gi < T2) {
            float ga = fmaf(base[gi],      sc, sh);
            float gb = fmaf(base[gi + T2], sc, sh);
            v = ga / (1.f + expf(-gb));
            v = v / (1.f + expf(-v));
        }
        us[i] = v;
    }
    __syncthreads();
    int tt = tid * 4;
    float uw[36];
#pragma unroll
    for (int q = 0; q < 9; q++) {
        float4 v = *(const float4*)&us[tt + q*4];
        uw[q*4+0] = v.x; uw[q*4+1] = v.y; uw[q*4+2] = v.z; uw[q*4+3] = v.w;
    }
    float bc = bias[c];
    float a0 = bc, a1 = bc, a2 = bc, a3 = bc;
#pragma unroll
    for (int k = 0; k < 32; k++) {
        float wv = wk[k];
        a0 = fmaf(wv, uw[k],     a0);
        a1 = fmaf(wv, uw[k + 1], a1);
        a2 = fmaf(wv, uw[k + 2], a2);
        a3 = fmaf(wv, uw[k + 3], a3);
    }
    float s = 0.f, ss = 0.f;
    float* dst = g_u2 + (b*CO + c)*T3 + t0 + tt;
    float av[4] = {a0, a1, a2, a3};
#pragma unroll
    for (int r = 0; r < 4; r++) {
        int t = t0 + tt + r;
        if (t < T3) { dst[r] = av[r]; s += av[r]; ss += av[r]*av[r]; }
    }
#pragma unroll
    for (int off = 16; off; off >>= 1) {
        s  += __shfl_xor_sync(0xffffffffu, s,  off);
        ss += __shfl_xor_sync(0xffffffffu, ss, off);
    }
    int wid = tid >> 5;
    if ((tid & 31) == 0) { rs[wid] = s; rss[wid] = ss; }
    __syncthreads();
    if (tid == 0) {
        float a = 0.f, q = 0.f;
        for (int i = 0; i < 8; i++) { a += rs[i]; q += rss[i]; }
        atomicAdd(&g_st2[b*2],     a);
        atomicAdd(&g_st2[b*2 + 1], q);
    }
}

// ---------------- precompute fused (enc ∘ pw2) matrix (parallel) ----------------
__global__ __launch_bounds__(256) void k_prep(const float* __restrict__ pw2w,
                                              const float* __restrict__ pw2b,
                                              const float* __restrict__ encw,
                                              const float* __restrict__ encb) {
    int i = blockIdx.x * 256 + threadIdx.x;
    if (i < HH*CO) {
        int d = i >> 5, cp = i & 31;
        float acc = 0.f;
#pragma unroll 8
        for (int c = 0; c < CO; c++)
            acc = fmaf(encw[c*HH + d], pw2w[c*CO + cp], acc);
        g_Wm[i] = acc;
    } else if (i < HH*CO + HH) {
        int d = i - HH*CO;
        float acc = encb[d];
#pragma unroll 8
        for (int c = 0; c < CO; c++)
            acc = fmaf(encw[c*HH + d], pw2b[c], acc);
        g_bv[d] = acc;
    }
}

// ---------------- GN2 apply + fused pw2∘enc -> h (packed) ----------------
__global__ __launch_bounds__(256) void k_enc(const float* __restrict__ g2,
                                             const float* __restrict__ b2) {
    __shared__ float un[CO][128];
    __shared__ float Wse[CO][66];
    int b = blockIdx.y, t0 = blockIdx.x * 128;
    int tid = threadIdx.x;
    float n = (float)(CO * T3);
    float m   = g_st2[b*2] / n;
    float var = g_st2[b*2 + 1] / n - m*m;
    float rstd = rsqrtf(var + EPSF);
    for (int i = tid; i < CO*128; i += 256) {
        int c = i >> 7, tt = i & 127;
        int t = t0 + tt;
        float v = (t < T3) ? g_u2[(b*CO + c)*T3 + t] : 0.f;
        un[c][tt] = (v - m) * rstd * g2[c] + b2[c];
    }
    for (int i = tid; i < HH*CO; i += 256) {
        int d = i >> 5, c = i & 31;
        Wse[c][d] = g_Wm[i];
    }
    __syncthreads();
    int tt = tid & 127, dg = tid >> 7;
    int d0 = dg * 32;
    ull acc[16];
#pragma unroll
    for (int p = 0; p < 16; p++) acc[p] = pk2(g_bv[d0 + 2*p], g_bv[d0 + 2*p + 1]);
    for (int c = 0; c < CO; c++) {
        float uv = un[c][tt];
        ull U = pk2(uv, uv);
#pragma unroll
        for (int p = 0; p < 16; p++) {
            ull wv = *(const ull*)&Wse[c][d0 + 2*p];
            acc[p] = ffma2(wv, U, acc[p]);
        }
    }
    int t = t0 + tt;
    if (t < T3) {
#pragma unroll
        for (int p = 0; p < 16; p++) {
            float a0, a1; upk2(acc[p], a0, a1);
            g_h[(b*HH + d0 + 2*p)*T3 + t]     = a0;
            g_h[(b*HH + d0 + 2*p + 1)*T3 + t] = a1;
        }
    }
}

// ---------------- scan pass A: per-segment carries (segments 0..6) ----------------
// u broadcast via shfl (no smem -> no false LDS/STS ordering on the hot path)
__global__ __launch_bounds__(128) void k_scA(int lay) {
    int lane = threadIdx.x & 31, wl = threadIdx.x >> 5;
    int wg = blockIdx.x * 4 + wl;            // 0..7167
    int bh = wg & 1023, p = wg >> 10;        // p in 0..6
    int b = bh >> 6, h = bh & 63;
    int cbase = (lay*HH + h)*32 + lane;
    ull Ar  = g_pAr [cbase];
    ull Ai  = g_pAi [cbase];
    ull NAi = g_pAin[cbase];
    const float* uin = g_h + (b*HH + h)*T3 + p*SEG;
    ull Sr = 0ull, Si = 0ull;
    float u = uin[lane];
    for (int c0 = 0; c0 < SEG; c0 += 32) {
        float unext = (c0 + 32 < SEG) ? uin[c0 + 32 + lane] : 0.f;
#pragma unroll
        for (int j = 0; j < 32; j++) {
            float uj = __shfl_sync(0xffffffffu, u, j);
            ull U = pk2(uj, uj);
            ull t = ffma2(NAi, Si, U);
            ull m = fmul2(Ai, Sr);
            Sr = ffma2(Ar, Sr, t);
            Si = ffma2(Ar, Si, m);
        }
        u = unext;
    }
    int ci = (p*BB*HH + bh)*32 + lane;
    g_carR[ci] = Sr;
    g_carI[ci] = Si;
}

// ---------------- scan pass C: combine carries, z-form output scan ----------------
__global__ __launch_bounds__(128) void k_scC(const float* __restrict__ D, int lay) {
    __shared__ ull ps[4][32*33];
    int lane = threadIdx.x & 31, wl = threadIdx.x >> 5;
    int wg = blockIdx.x * 4 + wl;            // 0..8191
    int bh = wg & 1023, p = wg >> 10;        // p in 0..7
    int b = bh >> 6, h = bh & 63;
    int cbase = (lay*HH + h)*32 + lane;
    ull Ar  = g_pAr [cbase];
    ull Ai  = g_pAi [cbase];
    ull NAi = g_pAin[cbase];
    ull CcR = g_pCr [cbase];
    ull CcI = g_pCi [cbase];
    ull CcIn= g_pCin[cbase];
    float Dh = D[lay*HH + h];
    // reconstruct segment-start state S_p from predecessors' carries
    ull Sr = 0ull, Si = 0ull;
    for (int q = 0; q < p; q++) {
        int k = p - 1 - q;
        int bp = ((lay*HH + h)*7 + k)*32 + lane;
        ull aPr  = g_aPr [bp];
        ull aPi  = g_aPi [bp];
        ull aPin = g_aPin[bp];
        int ci = (q*BB*HH + bh)*32 + lane;
        ull CqR = g_carR[ci], CqI = g_carI[ci];
        Sr = ffma2(aPr,  CqR, Sr);
        Sr = ffma2(aPin, CqI, Sr);
        Si = ffma2(aPr,  CqI, Si);
        Si = ffma2(aPi,  CqR, Si);
    }
    // z = Cc ⊙ S
    ull zr = ffma2(CcR, Sr, fmul2(CcIn, Si));
    ull zi = ffma2(CcR, Si, fmul2(CcI,  Sr));
    int t0 = p * SEG;
    int len = min(SEG, T3 - t0);
    const float* uin = g_h + (b*HH + h)*T3 + t0;
    float* yo = g_y + (b*HH + h)*T3 + t0;
    ull* psw = ps[wl];
    float u = (lane < len) ? uin[lane] : 0.f;
    for (int c0 = 0; c0 < len; c0 += 32) {
        int lc = min(32, len - c0);
        float uval = u;
        float unext = 0.f;
        {
            int tn = c0 + 32 + lane;
            if (tn < len) unext = uin[tn];
        }
        if (lc == 32) {
#pragma unroll
            for (int j = 0; j < 32; j++) {
                float uj = __shfl_sync(0xffffffffu, uval, j);
                ull U = pk2(uj, uj);
                ull t1 = ffma2(NAi, zi, fmul2(CcR, U));
                ull t3 = ffma2(Ai,  zr, fmul2(CcI, U));
                zr = ffma2(Ar, zr, t1);
                zi = ffma2(Ar, zi, t3);
                psw[lane*33 + j] = zr;
            }
        } else {
            for (int j = 0; j < lc; j++) {
                float uj = __shfl_sync(0xffffffffu, uval, j);
                ull U = pk2(uj, uj);
                ull t1 = ffma2(NAi, zi, fmul2(CcR, U));
                ull t3 = ffma2(Ai,  zr, fmul2(CcI, U));
                zr = ffma2(Ar, zr, t1);
                zi = ffma2(Ar, zi, t3);
                psw[lane*33 + j] = zr;
            }
        }
        __syncwarp();
        if (lane < lc) {
            ull acc0 = psw[lane];
            ull acc1 = psw[33 + lane];
#pragma unroll
            for (int k = 2; k < 32; k += 2) {
                acc0 = fadd2(acc0, psw[k*33 + lane]);
                acc1 = fadd2(acc1, psw[(k+1)*33 + lane]);
            }
            ull acc = fadd2(acc0, acc1);
            float plo, phi; upk2(acc, plo, phi);
            float yv = fmaf(Dh, uval, plo + phi);
            yv = 0.5f * yv * (1.f + erff(yv * 0.70710678118f));
            yo[c0 + lane] = yv;
        }
        __syncwarp();
        u = unext;
    }
}

// ---- mixer: smem-tiled ow GEMM (packed) + GLU(ch) + residual + LN(ch) ----
__global__ __launch_bounds__(256) void k_mix(const float* __restrict__ ow,
                                             const float* __restrict__ ob,
                                             const float* __restrict__ lg,
                                             const float* __restrict__ lb, int lay) {
    __shared__ float Ws[64][130];
    __shared__ float ys[64][32];
    __shared__ float rsum[8][32], rss2[8][32];
    __shared__ float mu[32], rstd[32];
    int b = blockIdx.y, t0 = blockIdx.x * 32;
    int tid = threadIdx.x;
    const float* owl = ow + lay*2*HH*HH;
    const float* obl = ob + lay*2*HH;
    for (int i = tid; i < 2*HH*HH; i += 256) {
        int j = i >> 6, k = i & 63;
        Ws[k][j] = owl[i];
    }
    for (int i = tid; i < HH*32; i += 256) {
        int ch = i >> 5, tt = i & 31;
        int t = t0 + tt;
        ys[ch][tt] = (t < T3) ? g_y[(b*HH + ch)*T3 + t] : 0.f;
    }
    __syncthreads();
    int chgrp = tid >> 3, tgrp = tid & 7;
    int ch0 = chgrp * 2, tsub = tgrp * 4;
    ull accA[4], accB[4];
    {
        ull ia = pk2(obl[ch0],      obl[ch0 + 1]);
        ull ib = pk2(obl[ch0 + 64], obl[ch0 + 65]);
#pragma unroll
        for (int t = 0; t < 4; t++) { accA[t] = ia; accB[t] = ib; }
    }
#pragma unroll 4
    for (int k = 0; k < 64; k++) {
        ull wa = *(const ull*)&Ws[k][ch0];
        ull wb = *(const ull*)&Ws[k][ch0 + 64];
        float4 yv = *(const float4*)&ys[k][tsub];
        ull y0 = pk2(yv.x, yv.x), y1 = pk2(yv.y, yv.y);
        ull y2 = pk2(yv.z, yv.z), y3 = pk2(yv.w, yv.w);
        accA[0] = ffma2(wa, y0, accA[0]);  accB[0] = ffma2(wb, y0, accB[0]);
        accA[1] = ffma2(wa, y1, accA[1]);  accB[1] = ffma2(wb, y1, accB[1]);
        accA[2] = ffma2(wa, y2, accA[2]);  accB[2] = ffma2(wb, y2, accB[2]);
        accA[3] = ffma2(wa, y3, accA[3]);  accB[3] = ffma2(wb, y3, accB[3]);
    }
    __syncthreads();
    float zr0[4], zr1[4];
#pragma unroll
    for (int t = 0; t < 4; t++) {
        int tg = t0 + tsub + t;
        float oa0, oa1, og0, og1;
        upk2(accA[t], oa0, oa1);
        upk2(accB[t], og0, og1);
        float h0 = 0.f, h1 = 0.f;
        if (tg < T3) {
            h0 = g_h[(b*HH + ch0)*T3 + tg];
            h1 = g_h[(b*HH + ch0 + 1)*T3 + tg];
        }
        float z0 = oa0 / (1.f + expf(-og0)) + h0;
        float z1 = oa1 / (1.f + expf(-og1)) + h1;
        zr0[t] = z0; zr1[t] = z1;
        ys[ch0][tsub + t]     = z0;
        ys[ch0 + 1][tsub + t] = z1;
    }
    __syncthreads();
    {
        int grp = tid >> 5, tsel = tid & 31;
        float s = 0.f, ss = 0.f;
#pragma unroll
        for (int q = 0; q < 8; q++) {
            float v = ys[grp*8 + q][tsel];
            s += v; ss += v*v;
        }
        rsum[grp][tsel] = s; rss2[grp][tsel] = ss;
    }
    __syncthreads();
    if (tid < 32) {
        float s = 0.f, ss = 0.f;
#pragma unroll
        for (int g = 0; g < 8; g++) { s += rsum[g][tid]; ss += rss2[g][tid]; }
        float m = s / 64.f;
        float var = ss / 64.f - m*m;
        mu[tid] = m; rstd[tid] = rsqrtf(var + EPSF);
    }
    __syncthreads();
    float lg0 = lg[lay*HH + ch0], lg1 = lg[lay*HH + ch0 + 1];
    float lb0 = lb[lay*HH + ch0], lb1 = lb[lay*HH + ch0 + 1];
#pragma unroll
    for (int t = 0; t < 4; t++) {
        int tg = t0 + tsub + t;
        if (tg < T3) {
            float m = mu[tsub + t], r = rstd[tsub + t];
            g_h[(b*HH + ch0)*T3 + tg]     = (zr0[t] - m) * r * lg0 + lb0;
            g_h[(b*HH + ch0 + 1)*T3 + tg] = (zr1[t] - m) * r * lg1 + lb1;
        }
    }
}

// ---------------- decoder: tiled packed GEMM (b,d,t)x(d,o) -> (b,t,o) ----------------
__global__ __launch_bounds__(256) void k_dec(const float* __restrict__ dw,
                                             const float* __restrict__ db,
                                             float* __restrict__ out) {
    __shared__ float wsd[HH][64];
    __shared__ float hsd[HH][64];
    int o0b = blockIdx.x * 64, t0 = blockIdx.y * 64, b = blockIdx.z;
    int tid = threadIdx.x;
    for (int i = tid; i < HH*64; i += 256) {
        int d = i >> 6, o = i & 63;
        wsd[d][o] = dw[d*DOUT + o0b + o];
    }
    for (int i = tid; i < HH*64; i += 256) {
        int d = i >> 6, tt = i & 63;
        int t = t0 + tt;
        hsd[d][tt] = (t < T3) ? g_h[(b*HH + d)*T3 + t] : 0.f;
    }
    __syncthreads();
    int ogrp = tid & 15, tgrp = tid >> 4;
    int o0 = ogrp * 4, tsub = tgrp * 4;
    ull accA[4], accB[4];
    {
        ull ia = pk2(db[o0b + o0],     db[o0b + o0 + 1]);
        ull ib = pk2(db[o0b + o0 + 2], db[o0b + o0 + 3]);
#pragma unroll
        for (int t = 0; t < 4; t++) { accA[t] = ia; accB[t] = ib; }
    }
#pragma unroll 4
    for (int k = 0; k < HH; k++) {
        ull wa = *(const ull*)&wsd[k][o0];
        ull wb = *(const ull*)&wsd[k][o0 + 2];
        float4 hv = *(const float4*)&hsd[k][tsub];
        ull h0 = pk2(hv.x, hv.x), h1 = pk2(hv.y, hv.y);
        ull h2 = pk2(hv.z, hv.z), h3 = pk2(hv.w, hv.w);
        accA[0] = ffma2(wa, h0, accA[0]);  accB[0] = ffma2(wb, h0, accB[0]);
        accA[1] = ffma2(wa, h1, accA[1]);  accB[1] = ffma2(wb, h1, accB[1]);
        accA[2] = ffma2(wa, h2, accA[2]);  accB[2] = ffma2(wb, h2, accB[2]);
        accA[3] = ffma2(wa, h3, accA[3]);  accB[3] = ffma2(wb, h3, accB[3]);
    }
#pragma unroll
    for (int t = 0; t < 4; t++) {
        int tg = t0 + tsub + t;
        if (tg < T3) {
            float4 o4;
            upk2(accA[t], o4.x, o4.y);
            upk2(accB[t], o4.z, o4.w);
            *(float4*)&out[((size_t)(b*T3 + tg))*DOUT + o0b + o0] = o4;
        }
    }
}

// ---------------- launcher ----------------
extern "C" void kernel_launch(void* const* d_in, const int* in_sizes, int n_in,
                              void* d_out, int out_size) {
    const float* x      = (const float*)d_in[0];
    const float* pw1w   = (const float*)d_in[1];
    const float* pw1b   = (const float*)d_in[2];
    const float* gn1g   = (const float*)d_in[3];
    const float* gn1b   = (const float*)d_in[4];
    const float* dww    = (const float*)d_in[5];
    const float* dwb    = (const float*)d_in[6];
    const float* gn2g   = (const float*)d_in[7];
    const float* gn2b   = (const float*)d_in[8];
    const float* pw2w   = (const float*)d_in[9];
    const float* pw2b   = (const float*)d_in[10];
    const float* encw   = (const float*)d_in[11];
    const float* encb   = (const float*)d_in[12];
    const float* logdt  = (const float*)d_in[13];
    const float* logA   = (const float*)d_in[14];
    const float* Aim    = (const float*)d_in[15];
    const float* Cre    = (const float*)d_in[16];
    const float* Cim    = (const float*)d_in[17];
    const float* s4D    = (const float*)d_in[18];
    const float* s4ow   = (const float*)d_in[19];
    const float* s4ob   = (const float*)d_in[20];
    const float* lng    = (const float*)d_in[21];
    const float* lnb    = (const float*)d_in[22];
    const float* decw   = (const float*)d_in[23];
    const float* decb   = (const float*)d_in[24];
    float* out = (float*)d_out;

    k_s4c<<<dim3(HH, NL), 64>>>(logdt, logA, Aim, Cre, Cim);
    k_pw1<<<dim3(T1/128, BB), 256>>>(x, pw1w, pw1b);
    k_dwf<<<dim3(2, CO, BB), 256>>>(dww, dwb, gn1g, gn1b);
    k_prep<<<9, 256>>>(pw2w, pw2b, encw, encb);
    k_enc<<<dim3(16, BB), 256>>>(gn2g, gn2b);
    for (int l = 0; l < NL; l++) {
        k_scA<<<(BB*HH*7)/4, 128>>>(l);
        k_scC<<<(BB*HH*NSEG)/4, 128>>>(s4D, l);
        k_mix<<<dim3(64, BB), 256>>>(s4ow, s4ob, lng, lnb, l);
    }
    k_dec<<<dim3(DOUT/64, 32, BB), 256>>>(decw, decb, out);
}

// round 9
// speedup vs baseline: 1.5764x; 1.0205x over previous
#include <cuda_runtime.h>
#include <math.h>

typedef unsigned long long ull;

// ---------------- problem constants ----------------
#define BB   16
#define C1   64
#define T1   4096
#define CO   32
#define T2   2048      // after GLU over time
#define T3   2019      // after depthwise conv k=32, pad(1,1)
#define HH   64        // d_model
#define NST  64        // S4 state size
#define NL   8
#define DOUT 640
#define EPSF 1e-5f
#define SEG  256       // scan segment length
#define NSEG 8

// ---------------- f32x2 packed helpers ----------------
__device__ __forceinline__ ull pk2(float a, float b) {
    ull r; asm("mov.b64 %0, {%1, %2};" : "=l"(r) : "f"(a), "f"(b)); return r;
}
__device__ __forceinline__ void upk2(ull v, float& a, float& b) {
    asm("mov.b64 {%0, %1}, %2;" : "=f"(a), "=f"(b) : "l"(v));
}
__device__ __forceinline__ ull ffma2(ull a, ull b, ull c) {
    ull r; asm("fma.rn.f32x2 %0, %1, %2, %3;" : "=l"(r) : "l"(a), "l"(b), "l"(c)); return r;
}
__device__ __forceinline__ ull fmul2(ull a, ull b) {
    ull r; asm("mul.rn.f32x2 %0, %1, %2;" : "=l"(r) : "l"(a), "l"(b)); return r;
}

// ---------------- scratch (device globals; no allocation) ----------------
__device__ float g_u1[BB*CO*T1];
__device__ float g_u2[BB*CO*T3];
__device__ float g_h [BB*HH*T3];
__device__ float g_y [BB*HH*T3];
__device__ float g_st1[BB*2];
__device__ float g_st2[BB*2];
__device__ float g_Wm [HH*CO];
__device__ float g_bv [HH];

__device__ ull g_pAr [NL*HH*32];
__device__ ull g_pAi [NL*HH*32];
__device__ ull g_pAin[NL*HH*32];
__device__ ull g_pCr [NL*HH*32];
__device__ ull g_pCi [NL*HH*32];
__device__ ull g_pCin[NL*HH*32];
__device__ ull g_aPr [NL*HH*7*32];
__device__ ull g_aPi [NL*HH*7*32];
__device__ ull g_aPin[NL*HH*7*32];
__device__ ull g_carR[7*BB*HH*32];
__device__ ull g_carI[7*BB*HH*32];
__device__ int g_flag[NL*7*BB*HH];    // publish flags per (lay, seg 0..6, bh)

// ---------------- S4D constants + power tables + flag/stat zero ----------------
__global__ void k_s4c(const float* __restrict__ logdt, const float* __restrict__ logA,
                      const float* __restrict__ Aim,  const float* __restrict__ Cre,
                      const float* __restrict__ Cim) {
    __shared__ float s_ar[64], s_ai[64], s_cr[64], s_ci[64];
    __shared__ float s_pr[7][64], s_pi[7][64];
    int h = blockIdx.x, lay = blockIdx.y, n = threadIdx.x;
    if (h == 0 && lay == 0 && n < BB*2) { g_st1[n] = 0.f; g_st2[n] = 0.f; }
    {   // zero the publish flags (every launch / replay)
        int gidx = (lay*HH + h)*64 + n;
        for (int i = gidx; i < NL*7*BB*HH; i += NL*HH*64) g_flag[i] = 0;
    }
    int src = (lay*HH + h)*NST + n;
    float dt  = expf(logdt[lay*HH + h]);
    float Are = -expf(logA[src]);
    float Aii = Aim[src];
    float e = expf(Are * dt);
    float are = e * cosf(Aii * dt);
    float aim = e * sinf(Aii * dt);
    float nre = are - 1.f, nim = aim;
    float den = Are*Are + Aii*Aii;
    float qre = (nre*Are + nim*Aii) / den;
    float qim = (nim*Are - nre*Aii) / den;
    float cre = Cre[src], cim = Cim[src];
    s_ar[n] = are; s_ai[n] = aim;
    s_cr[n] = 2.f*(cre*qre - cim*qim);
    s_ci[n] = 2.f*(cre*qim + cim*qre);
    float qr = are, qi = aim;
#pragma unroll
    for (int s = 0; s < 8; s++) {
        float nr = qr*qr - qi*qi, ni = 2.f*qr*qi;
        qr = nr; qi = ni;
    }
    float Pr = 1.f, Pi = 0.f;
    s_pr[0][n] = 1.f; s_pi[0][n] = 0.f;
#pragma unroll
    for (int k = 1; k < 7; k++) {
        float nr = Pr*qr - Pi*qi, ni = Pr*qi + Pi*qr;
        Pr = nr; Pi = ni;
        s_pr[k][n] = Pr; s_pi[k][n] = Pi;
    }
    __syncthreads();
    if (n < 32) {
        int base = (lay*HH + h)*32 + n;
        g_pAr [base] = pk2(s_ar[n],  s_ar[n+32]);
        g_pAi [base] = pk2(s_ai[n],  s_ai[n+32]);
        g_pAin[base] = pk2(-s_ai[n], -s_ai[n+32]);
        g_pCr [base] = pk2(s_cr[n],  s_cr[n+32]);
        g_pCi [base] = pk2(s_ci[n],  s_ci[n+32]);
        g_pCin[base] = pk2(-s_ci[n], -s_ci[n+32]);
#pragma unroll
        for (int k = 0; k < 7; k++) {
            int bp = ((lay*HH + h)*7 + k)*32 + n;
            g_aPr [bp] = pk2(s_pr[k][n],  s_pr[k][n+32]);
            g_aPi [bp] = pk2(s_pi[k][n],  s_pi[k][n+32]);
            g_aPin[bp] = pk2(-s_pi[k][n], -s_pi[k][n+32]);
        }
    }
}

// ---------------- pw1 (64->32 pointwise, packed) + GN1 stats ----------------
__global__ __launch_bounds__(256) void k_pw1(const float* __restrict__ x,
                                             const float* __restrict__ w,
                                             const float* __restrict__ bias) {
    __shared__ float xs[C1][128];
    __shared__ float wst[C1][34];
    __shared__ float rs[8], rss[8];
    int b = blockIdx.y, t0 = blockIdx.x * 128;
    int tid = threadIdx.x;
    for (int i = tid; i < C1*128; i += 256) {
        int c = i >> 7, tt = i & 127;
        xs[c][tt] = x[(b*C1 + c)*T1 + t0 + tt];
    }
    for (int i = tid; i < CO*C1; i += 256) {
        int o = i >> 6, c = i & 63;
        wst[c][o] = w[i];
    }
    __syncthreads();
    int tt = tid & 127, half = tid >> 7;
    int ob0 = half * 16;
    ull acc[8];
#pragma unroll
    for (int p = 0; p < 8; p++) acc[p] = pk2(bias[ob0 + 2*p], bias[ob0 + 2*p + 1]);
    for (int c = 0; c < C1; c++) {
        float xv = xs[c][tt];
        ull X = pk2(xv, xv);
#pragma unroll
        for (int p = 0; p < 8; p++) {
            ull wv = *(const ull*)&wst[c][ob0 + 2*p];
            acc[p] = ffma2(wv, X, acc[p]);
        }
    }
    float s = 0.f, ss = 0.f;
#pragma unroll
    for (int p = 0; p < 8; p++) {
        float a0, a1; upk2(acc[p], a0, a1);
        int o = ob0 + 2*p;
        g_u1[(b*CO + o)*T1 + t0 + tt]     = a0;
        g_u1[(b*CO + o + 1)*T1 + t0 + tt] = a1;
        s += a0 + a1; ss += a0*a0 + a1*a1;
    }
#pragma unroll
    for (int off = 16; off; off >>= 1) {
        s  += __shfl_xor_sync(0xffffffffu, s,  off);
        ss += __shfl_xor_sync(0xffffffffu, ss, off);
    }
    int wid = tid >> 5;
    if ((tid & 31) == 0) { rs[wid] = s; rss[wid] = ss; }
    __syncthreads();
    if (tid == 0) {
        float a = 0.f, q = 0.f;
        for (int i = 0; i < 8; i++) { a += rs[i]; q += rss[i]; }
        atomicAdd(&g_st1[b*2],     a);
        atomicAdd(&g_st1[b*2 + 1], q);
    }
}

// ---- fused GN1-apply + GLU(time) + SiLU + depthwise conv (k=32) + GN2 stats ----
__global__ __launch_bounds__(256) void k_dwf(const float* __restrict__ w,
                                             const float* __restrict__ bias,
                                             const float* __restrict__ g1,
                                             const float* __restrict__ b1) {
    __shared__ float us[1024 + 36];
    __shared__ float wk[32];
    __shared__ float rs[8], rss[8];
    int t0 = blockIdx.x * 1024, c = blockIdx.y, b = blockIdx.z;
    int tid = threadIdx.x;
    if (tid < 32) wk[tid] = w[c*32 + tid];
    float n1 = (float)(CO * T1);
    float m1   = g_st1[b*2] / n1;
    float var1 = g_st1[b*2 + 1] / n1 - m1*m1;
    float rstd1 = rsqrtf(var1 + EPSF);
    float sc = rstd1 * g1[c], sh = b1[c] - m1 * sc;
    const float* base = g_u1 + (b*CO + c)*T1;
    for (int i = tid; i < 1060; i += 256) {
        int gi = t0 - 1 + i;
        float v = 0.f;
        if (gi >= 0 && gi < T2) {
            float ga = fmaf(base[gi],      sc, sh);
            float gb = fmaf(base[gi + T2], sc, sh);
            v = ga / (1.f + __expf(-gb));
            v = v / (1.f + __expf(-v));
        }
        us[i] = v;
    }
    __syncthreads();
    int tt = tid * 4;
    float uw[36];
#pragma unroll
    for (int q = 0; q < 9; q++) {
        float4 v = *(const float4*)&us[tt + q*4];
        uw[q*4+0] = v.x; uw[q*4+1] = v.y; uw[q*4+2] = v.z; uw[q*4+3] = v.w;
    }
    float bc = bias[c];
    float a0 = bc, a1 = bc, a2 = bc, a3 = bc;
#pragma unroll
    for (int k = 0; k < 32; k++) {
        float wv = wk[k];
        a0 = fmaf(wv, uw[k],     a0);
        a1 = fmaf(wv, uw[k + 1], a1);
        a2 = fmaf(wv, uw[k + 2], a2);
        a3 = fmaf(wv, uw[k + 3], a3);
    }
    float s = 0.f, ss = 0.f;
    float* dst = g_u2 + (b*CO + c)*T3 + t0 + tt;
    float av[4] = {a0, a1, a2, a3};
#pragma unroll
    for (int r = 0; r < 4; r++) {
        int t = t0 + tt + r;
        if (t < T3) { dst[r] = av[r]; s += av[r]; ss += av[r]*av[r]; }
    }
#pragma unroll
    for (int off = 16; off; off >>= 1) {
        s  += __shfl_xor_sync(0xffffffffu, s,  off);
        ss += __shfl_xor_sync(0xffffffffu, ss, off);
    }
    int wid = tid >> 5;
    if ((tid & 31) == 0) { rs[wid] = s; rss[wid] = ss; }
    __syncthreads();
    if (tid == 0) {
        float a = 0.f, q = 0.f;
        for (int i = 0; i < 8; i++) { a += rs[i]; q += rss[i]; }
        atomicAdd(&g_st2[b*2],     a);
        atomicAdd(&g_st2[b*2 + 1], q);
    }
}

// ---------------- precompute fused (enc ∘ pw2) matrix (parallel) ----------------
__global__ __launch_bounds__(256) void k_prep(const float* __restrict__ pw2w,
                                              const float* __restrict__ pw2b,
                                              const float* __restrict__ encw,
                                              const float* __restrict__ encb) {
    int i = blockIdx.x * 256 + threadIdx.x;
    if (i < HH*CO) {
        int d = i >> 5, cp = i & 31;
        float acc = 0.f;
#pragma unroll 8
        for (int c = 0; c < CO; c++)
            acc = fmaf(encw[c*HH + d], pw2w[c*CO + cp], acc);
        g_Wm[i] = acc;
    } else if (i < HH*CO + HH) {
        int d = i - HH*CO;
        float acc = encb[d];
#pragma unroll 8
        for (int c = 0; c < CO; c++)
            acc = fmaf(encw[c*HH + d], pw2b[c], acc);
        g_bv[d] = acc;
    }
}

// ---------------- GN2 apply + fused pw2∘enc -> h (packed) ----------------
__global__ __launch_bounds__(256) void k_enc(const float* __restrict__ g2,
                                             const float* __restrict__ b2) {
    __shared__ float un[CO][128];
    __shared__ float Wse[CO][66];
    int b = blockIdx.y, t0 = blockIdx.x * 128;
    int tid = threadIdx.x;
    float n = (float)(CO * T3);
    float m   = g_st2[b*2] / n;
    float var = g_st2[b*2 + 1] / n - m*m;
    float rstd = rsqrtf(var + EPSF);
    for (int i = tid; i < CO*128; i += 256) {
        int c = i >> 7, tt = i & 127;
        int t = t0 + tt;
        float v = (t < T3) ? g_u2[(b*CO + c)*T3 + t] : 0.f;
        un[c][tt] = (v - m) * rstd * g2[c] + b2[c];
    }
    for (int i = tid; i < HH*CO; i += 256) {
        int d = i >> 5, c = i & 31;
        Wse[c][d] = g_Wm[i];
    }
    __syncthreads();
    int tt = tid & 127, dg = tid >> 7;
    int d0 = dg * 32;
    ull acc[16];
#pragma unroll
    for (int p = 0; p < 16; p++) acc[p] = pk2(g_bv[d0 + 2*p], g_bv[d0 + 2*p + 1]);
    for (int c = 0; c < CO; c++) {
        float uv = un[c][tt];
        ull U = pk2(uv, uv);
#pragma unroll
        for (int p = 0; p < 16; p++) {
            ull wv = *(const ull*)&Wse[c][d0 + 2*p];
            acc[p] = ffma2(wv, U, acc[p]);
        }
    }
    int t = t0 + tt;
    if (t < T3) {
#pragma unroll
        for (int p = 0; p < 16; p++) {
            float a0, a1; upk2(acc[p], a0, a1);
            g_h[(b*HH + d0 + 2*p)*T3 + t]     = a0;
            g_h[(b*HH + d0 + 2*p + 1)*T3 + t] = a1;
        }
    }
}

// ---------------- fused S4D scan: carry phase + flag handshake + output ----------------
__global__ __launch_bounds__(128) void k_sc(const float* __restrict__ D, int lay) {
    __shared__ float ps[4][32*33];
    int lane = threadIdx.x & 31, wl = threadIdx.x >> 5;
    int wg = blockIdx.x * 4 + wl;            // 0..8191
    int bh = wg & 1023, p = wg >> 10;        // seg p in 0..7
    int b = bh >> 6, h = bh & 63;
    int cbase = (lay*HH + h)*32 + lane;
    ull Ar  = g_pAr [cbase];
    ull Ai  = g_pAi [cbase];
    ull NAi = g_pAin[cbase];
    ull CcR = g_pCr [cbase];
    ull CcI = g_pCi [cbase];
    ull CcIn= g_pCin[cbase];
    float Dh = D[lay*HH + h];
    int t0 = p * SEG;
    int len = min(SEG, T3 - t0);             // 256, or 227 for p=7
    const float* uin = g_h + (b*HH + h)*T3 + t0;
    float* yo = g_y + (b*HH + h)*T3 + t0;
    // load full segment's u into registers (zero-padded tail)
    float u[8];
#pragma unroll
    for (int ci = 0; ci < 8; ci++) {
        int t = ci*32 + lane;
        u[ci] = (t < len) ? uin[t] : 0.f;
    }
    // ---- phase 1: compute + publish this segment's carry (segments 0..6) ----
    if (p < 7) {
        ull Sr = 0ull, Si = 0ull;
#pragma unroll
        for (int ci = 0; ci < 8; ci++) {
            float uc = u[ci];
#pragma unroll
            for (int j = 0; j < 32; j++) {
                float uj = __shfl_sync(0xffffffffu, uc, j);
                ull U = pk2(uj, uj);
                ull t = ffma2(NAi, Si, U);
                ull m = fmul2(Ai, Sr);
                Sr = ffma2(Ar, Sr, t);
                Si = ffma2(Ar, Si, m);
            }
        }
        int ci2 = (p*BB*HH + bh)*32 + lane;
        g_carR[ci2] = Sr;
        g_carI[ci2] = Si;
        __syncwarp();
        __threadfence();
        if (lane == 0)
            *((volatile int*)&g_flag[(lay*7 + p)*BB*HH + bh]) = 1;
    }
    // ---- wait for predecessors' carries ----
    for (int q = 0; q < p; q++) {
        volatile int* f = &g_flag[(lay*7 + q)*BB*HH + bh];
        while (*f == 0) __nanosleep(64);
    }
    __threadfence();
    // ---- reconstruct segment-start state ----
    ull Sr = 0ull, Si = 0ull;
    for (int q = 0; q < p; q++) {
        int k = p - 1 - q;
        int bp = ((lay*HH + h)*7 + k)*32 + lane;
        ull aPr  = g_aPr [bp];
        ull aPi  = g_aPi [bp];
        ull aPin = g_aPin[bp];
        int ci2 = (q*BB*HH + bh)*32 + lane;
        ull CqR = g_carR[ci2], CqI = g_carI[ci2];
        Sr = ffma2(aPr,  CqR, Sr);
        Sr = ffma2(aPin, CqI, Sr);
        Si = ffma2(aPr,  CqI, Si);
        Si = ffma2(aPi,  CqR, Si);
    }
    // z = Cc ⊙ S
    ull zr = ffma2(CcR, Sr, fmul2(CcIn, Si));
    ull zi = ffma2(CcR, Si, fmul2(CcI,  Sr));
    float* psw = ps[wl];
    // ---- phase 2: output scan, chunks 0..6 always full ----
#pragma unroll
    for (int ci = 0; ci < 7; ci++) {
        float uc = u[ci];
#pragma unroll
        for (int j = 0; j < 32; j++) {
            float uj = __shfl_sync(0xffffffffu, uc, j);
            ull U = pk2(uj, uj);
            ull t1 = ffma2(NAi, zi, fmul2(CcR, U));
            ull t3 = ffma2(Ai,  zr, fmul2(CcI, U));
            zr = ffma2(Ar, zr, t1);
            zi = ffma2(Ar, zi, t3);
            float lo, hi; upk2(zr, lo, hi);
            psw[lane*33 + j] = lo + hi;
        }
        __syncwarp();
        {
            float acc = psw[lane];
#pragma unroll
            for (int k = 1; k < 32; k++) acc += psw[k*33 + lane];
            float yv = fmaf(Dh, uc, acc);
            yv = 0.5f * yv * (1.f + erff(yv * 0.70710678118f));
            yo[ci*32 + lane] = yv;
        }
        __syncwarp();
    }
    // ---- tail chunk 7 (lc = 32 or 3) ----
    {
        int lc = len - 224;
        float uc = u[7];
        for (int j = 0; j < lc; j++) {
            float uj = __shfl_sync(0xffffffffu, uc, j);
            ull U = pk2(uj, uj);
            ull t1 = ffma2(NAi, zi, fmul2(CcR, U));
            ull t3 = ffma2(Ai,  zr, fmul2(CcI, U));
            zr = ffma2(Ar, zr, t1);
            zi = ffma2(Ar, zi, t3);
            float lo, hi; upk2(zr, lo, hi);
            psw[lane*33 + j] = lo + hi;
        }
        __syncwarp();
        if (lane < lc) {
            float acc = psw[lane];
#pragma unroll
            for (int k = 1; k < 32; k++) acc += psw[k*33 + lane];
            float yv = fmaf(Dh, uc, acc);
            yv = 0.5f * yv * (1.f + erff(yv * 0.70710678118f));
            yo[224 + lane] = yv;
        }
    }
}

// ---- mixer: smem-tiled ow GEMM (packed) + GLU(ch) + residual + LN(ch) ----
__global__ __launch_bounds__(256) void k_mix(const float* __restrict__ ow,
                                             const float* __restrict__ ob,
                                             const float* __restrict__ lg,
                                             const float* __restrict__ lb, int lay) {
    __shared__ float Ws[64][130];
    __shared__ float ys[64][32];
    __shared__ float rsum[8][32], rss2[8][32];
    __shared__ float mu[32], rstd[32];
    int b = blockIdx.y, t0 = blockIdx.x * 32;
    int tid = threadIdx.x;
    const float* owl = ow + lay*2*HH*HH;
    const float* obl = ob + lay*2*HH;
    for (int i = tid; i < 2*HH*HH; i += 256) {
        int j = i >> 6, k = i & 63;
        Ws[k][j] = owl[i];
    }
    for (int i = tid; i < HH*32; i += 256) {
        int ch = i >> 5, tt = i & 31;
        int t = t0 + tt;
        ys[ch][tt] = (t < T3) ? g_y[(b*HH + ch)*T3 + t] : 0.f;
    }
    __syncthreads();
    int chgrp = tid >> 3, tgrp = tid & 7;
    int ch0 = chgrp * 2, tsub = tgrp * 4;
    ull accA[4], accB[4];
    {
        ull ia = pk2(obl[ch0],      obl[ch0 + 1]);
        ull ib = pk2(obl[ch0 + 64], obl[ch0 + 65]);
#pragma unroll
        for (int t = 0; t < 4; t++) { accA[t] = ia; accB[t] = ib; }
    }
#pragma unroll 4
    for (int k = 0; k < 64; k++) {
        ull wa = *(const ull*)&Ws[k][ch0];
        ull wb = *(const ull*)&Ws[k][ch0 + 64];
        float4 yv = *(const float4*)&ys[k][tsub];
        ull y0 = pk2(yv.x, yv.x), y1 = pk2(yv.y, yv.y);
        ull y2 = pk2(yv.z, yv.z), y3 = pk2(yv.w, yv.w);
        accA[0] = ffma2(wa, y0, accA[0]);  accB[0] = ffma2(wb, y0, accB[0]);
        accA[1] = ffma2(wa, y1, accA[1]);  accB[1] = ffma2(wb, y1, accB[1]);
        accA[2] = ffma2(wa, y2, accA[2]);  accB[2] = ffma2(wb, y2, accB[2]);
        accA[3] = ffma2(wa, y3, accA[3]);  accB[3] = ffma2(wb, y3, accB[3]);
    }
    __syncthreads();
    float zr0[4], zr1[4];
#pragma unroll
    for (int t = 0; t < 4; t++) {
        int tg = t0 + tsub + t;
        float oa0, oa1, og0, og1;
        upk2(accA[t], oa0, oa1);
        upk2(accB[t], og0, og1);
        float h0 = 0.f, h1 = 0.f;
        if (tg < T3) {
            h0 = g_h[(b*HH + ch0)*T3 + tg];
            h1 = g_h[(b*HH + ch0 + 1)*T3 + tg];
        }
        float z0 = oa0 / (1.f + __expf(-og0)) + h0;
        float z1 = oa1 / (1.f + __expf(-og1)) + h1;
        zr0[t] = z0; zr1[t] = z1;
        ys[ch0][tsub + t]     = z0;
        ys[ch0 + 1][tsub + t] = z1;
    }
    __syncthreads();
    {
        int grp = tid >> 5, tsel = tid & 31;
        float s = 0.f, ss = 0.f;
#pragma unroll
        for (int q = 0; q < 8; q++) {
            float v = ys[grp*8 + q][tsel];
            s += v; ss += v*v;
        }
        rsum[grp][tsel] = s; rss2[grp][tsel] = ss;
    }
    __syncthreads();
    if (tid < 32) {
        float s = 0.f, ss = 0.f;
#pragma unroll
        for (int g = 0; g < 8; g++) { s += rsum[g][tid]; ss += rss2[g][tid]; }
        float m = s / 64.f;
        float var = ss / 64.f - m*m;
        mu[tid] = m; rstd[tid] = rsqrtf(var + EPSF);
    }
    __syncthreads();
    float lg0 = lg[lay*HH + ch0], lg1 = lg[lay*HH + ch0 + 1];
    float lb0 = lb[lay*HH + ch0], lb1 = lb[lay*HH + ch0 + 1];
#pragma unroll
    for (int t = 0; t < 4; t++) {
        int tg = t0 + tsub + t;
        if (tg < T3) {
            float m = mu[tsub + t], r = rstd[tsub + t];
            g_h[(b*HH + ch0)*T3 + tg]     = (zr0[t] - m) * r * lg0 + lb0;
            g_h[(b*HH + ch0 + 1)*T3 + tg] = (zr1[t] - m) * r * lg1 + lb1;
        }
    }
}

// ---------------- decoder: tiled packed GEMM (b,d,t)x(d,o) -> (b,t,o) ----------------
__global__ __launch_bounds__(256) void k_dec(const float* __restrict__ dw,
                                             const float* __restrict__ db,
                                             float* __restrict__ out) {
    __shared__ float wsd[HH][64];
    __shared__ float hsd[HH][64];
    int o0b = blockIdx.x * 64, t0 = blockIdx.y * 64, b = blockIdx.z;
    int tid = threadIdx.x;
    for (int i = tid; i < HH*64; i += 256) {
        int d = i >> 6, o = i & 63;
        wsd[d][o] = dw[d*DOUT + o0b + o];
    }
    for (int i = tid; i < HH*64; i += 256) {
        int d = i >> 6, tt = i & 63;
        int t = t0 + tt;
        hsd[d][tt] = (t < T3) ? g_h[(b*HH + d)*T3 + t] : 0.f;
    }
    __syncthreads();
    int ogrp = tid & 15, tgrp = tid >> 4;
    int o0 = ogrp * 4, tsub = tgrp * 4;
    ull accA[4], accB[4];
    {
        ull ia = pk2(db[o0b + o0],     db[o0b + o0 + 1]);
        ull ib = pk2(db[o0b + o0 + 2], db[o0b + o0 + 3]);
#pragma unroll
        for (int t = 0; t < 4; t++) { accA[t] = ia; accB[t] = ib; }
    }
#pragma unroll 4
    for (int k = 0; k < HH; k++) {
        ull wa = *(const ull*)&wsd[k][o0];
        ull wb = *(const ull*)&wsd[k][o0 + 2];
        float4 hv = *(const float4*)&hsd[k][tsub];
        ull h0 = pk2(hv.x, hv.x), h1 = pk2(hv.y, hv.y);
        ull h2 = pk2(hv.z, hv.z), h3 = pk2(hv.w, hv.w);
        accA[0] = ffma2(wa, h0, accA[0]);  accB[0] = ffma2(wb, h0, accB[0]);
        accA[1] = ffma2(wa, h1, accA[1]);  accB[1] = ffma2(wb, h1, accB[1]);
        accA[2] = ffma2(wa, h2, accA[2]);  accB[2] = ffma2(wb, h2, accB[2]);
        accA[3] = ffma2(wa, h3, accA[3]);  accB[3] = ffma2(wb, h3, accB[3]);
    }
#pragma unroll
    for (int t = 0; t < 4; t++) {
        int tg = t0 + tsub + t;
        if (tg < T3) {
            float4 o4;
            upk2(accA[t], o4.x, o4.y);
            upk2(accB[t], o4.z, o4.w);
            *(float4*)&out[((size_t)(b*T3 + tg))*DOUT + o0b + o0] = o4;
        }
    }
}

// ---------------- launcher ----------------
extern "C" void kernel_launch(void* const* d_in, const int* in_sizes, int n_in,
                              void* d_out, int out_size) {
    const float* x      = (const float*)d_in[0];
    const float* pw1w   = (const float*)d_in[1];
    const float* pw1b   = (const float*)d_in[2];
    const float* gn1g   = (const float*)d_in[3];
    const float* gn1b   = (const float*)d_in[4];
    const float* dww    = (const float*)d_in[5];
    const float* dwb    = (const float*)d_in[6];
    const float* gn2g   = (const float*)d_in[7];
    const float* gn2b   = (const float*)d_in[8];
    const float* pw2w   = (const float*)d_in[9];
    const float* pw2b   = (const float*)d_in[10];
    const float* encw   = (const float*)d_in[11];
    const float* encb   = (const float*)d_in[12];
    const float* logdt  = (const float*)d_in[13];
    const float* logA   = (const float*)d_in[14];
    const float* Aim    = (const float*)d_in[15];
    const float* Cre    = (const float*)d_in[16];
    const float* Cim    = (const float*)d_in[17];
    const float* s4D    = (const float*)d_in[18];
    const float* s4ow   = (const float*)d_in[19];
    const float* s4ob   = (const float*)d_in[20];
    const float* lng    = (const float*)d_in[21];
    const float* lnb    = (const float*)d_in[22];
    const float* decw   = (const float*)d_in[23];
    const float* decb   = (const float*)d_in[24];
    float* out = (float*)d_out;

    k_s4c<<<dim3(HH, NL), 64>>>(logdt, logA, Aim, Cre, Cim);
    k_pw1<<<dim3(T1/128, BB), 256>>>(x, pw1w, pw1b);
    k_dwf<<<dim3(2, CO, BB), 256>>>(dww, dwb, gn1g, gn1b);
    k_prep<<<9, 256>>>(pw2w, pw2b, encw, encb);
    k_enc<<<dim3(16, BB), 256>>>(gn2g, gn2b);
    for (int l = 0; l < NL; l++) {
        k_sc<<<(BB*HH*NSEG)/4, 128>>>(s4D, l);
        k_mix<<<dim3(64, BB), 256>>>(s4ow, s4ob, lng, lnb, l);
    }
    k_dec<<<dim3(DOUT/64, 32, BB), 256>>>(decw, decb, out);
}

// round 10
// speedup vs baseline: 1.5808x; 1.0027x over previous
#include <cuda_runtime.h>
#include <math.h>

typedef unsigned long long ull;

// ---------------- problem constants ----------------
#define BB   16
#define C1   64
#define T1   4096
#define CO   32
#define T2   2048      // after GLU over time
#define T3   2019      // after depthwise conv k=32, pad(1,1)
#define HH   64        // d_model
#define NST  64        // S4 state size
#define NL   8
#define DOUT 640
#define EPSF 1e-5f
#define SEG  256       // scan segment length
#define NSEG 8

// ---------------- f32x2 packed helpers ----------------
__device__ __forceinline__ ull pk2(float a, float b) {
    ull r; asm("mov.b64 %0, {%1, %2};" : "=l"(r) : "f"(a), "f"(b)); return r;
}
__device__ __forceinline__ void upk2(ull v, float& a, float& b) {
    asm("mov.b64 {%0, %1}, %2;" : "=f"(a), "=f"(b) : "l"(v));
}
__device__ __forceinline__ ull ffma2(ull a, ull b, ull c) {
    ull r; asm("fma.rn.f32x2 %0, %1, %2, %3;" : "=l"(r) : "l"(a), "l"(b), "l"(c)); return r;
}
__device__ __forceinline__ ull fmul2(ull a, ull b) {
    ull r; asm("mul.rn.f32x2 %0, %1, %2;" : "=l"(r) : "l"(a), "l"(b)); return r;
}

// ---------------- scratch (device globals; no allocation) ----------------
__device__ float g_u1[BB*CO*T1];
__device__ float g_u2[BB*CO*T3];
__device__ float g_h [BB*HH*T3];
__device__ float g_y [BB*HH*T3];
__device__ float g_st1[BB*2];
__device__ float g_st2[BB*2];
__device__ float g_Wm [HH*CO];
__device__ float g_bv [HH];

__device__ ull g_pAr [NL*HH*32];
__device__ ull g_pAi [NL*HH*32];
__device__ ull g_pAin[NL*HH*32];
__device__ ull g_pCr [NL*HH*32];
__device__ ull g_pCi [NL*HH*32];
__device__ ull g_pCin[NL*HH*32];
__device__ ull g_aPr [NL*HH*7*32];
__device__ ull g_aPi [NL*HH*7*32];
__device__ ull g_aPin[NL*HH*7*32];
__device__ ull g_carR[7*BB*HH*32];
__device__ ull g_carI[7*BB*HH*32];
__device__ int g_flag[NL*7*BB*HH];    // publish flags per (lay, seg 0..6, bh)

// ---------------- S4D constants + power tables + flag/stat zero ----------------
__global__ void k_s4c(const float* __restrict__ logdt, const float* __restrict__ logA,
                      const float* __restrict__ Aim,  const float* __restrict__ Cre,
                      const float* __restrict__ Cim) {
    __shared__ float s_ar[64], s_ai[64], s_cr[64], s_ci[64];
    __shared__ float s_pr[7][64], s_pi[7][64];
    int h = blockIdx.x, lay = blockIdx.y, n = threadIdx.x;
    if (h == 0 && lay == 0 && n < BB*2) { g_st1[n] = 0.f; g_st2[n] = 0.f; }
    {   // zero the publish flags (every launch / replay)
        int gidx = (lay*HH + h)*64 + n;
        for (int i = gidx; i < NL*7*BB*HH; i += NL*HH*64) g_flag[i] = 0;
    }
    int src = (lay*HH + h)*NST + n;
    float dt  = expf(logdt[lay*HH + h]);
    float Are = -expf(logA[src]);
    float Aii = Aim[src];
    float e = expf(Are * dt);
    float are = e * cosf(Aii * dt);
    float aim = e * sinf(Aii * dt);
    float nre = are - 1.f, nim = aim;
    float den = Are*Are + Aii*Aii;
    float qre = (nre*Are + nim*Aii) / den;
    float qim = (nim*Are - nre*Aii) / den;
    float cre = Cre[src], cim = Cim[src];
    s_ar[n] = are; s_ai[n] = aim;
    s_cr[n] = 2.f*(cre*qre - cim*qim);
    s_ci[n] = 2.f*(cre*qim + cim*qre);
    float qr = are, qi = aim;
#pragma unroll
    for (int s = 0; s < 8; s++) {
        float nr = qr*qr - qi*qi, ni = 2.f*qr*qi;
        qr = nr; qi = ni;
    }
    float Pr = 1.f, Pi = 0.f;
    s_pr[0][n] = 1.f; s_pi[0][n] = 0.f;
#pragma unroll
    for (int k = 1; k < 7; k++) {
        float nr = Pr*qr - Pi*qi, ni = Pr*qi + Pi*qr;
        Pr = nr; Pi = ni;
        s_pr[k][n] = Pr; s_pi[k][n] = Pi;
    }
    __syncthreads();
    if (n < 32) {
        int base = (lay*HH + h)*32 + n;
        g_pAr [base] = pk2(s_ar[n],  s_ar[n+32]);
        g_pAi [base] = pk2(s_ai[n],  s_ai[n+32]);
        g_pAin[base] = pk2(-s_ai[n], -s_ai[n+32]);
        g_pCr [base] = pk2(s_cr[n],  s_cr[n+32]);
        g_pCi [base] = pk2(s_ci[n],  s_ci[n+32]);
        g_pCin[base] = pk2(-s_ci[n], -s_ci[n+32]);
#pragma unroll
        for (int k = 0; k < 7; k++) {
            int bp = ((lay*HH + h)*7 + k)*32 + n;
            g_aPr [bp] = pk2(s_pr[k][n],  s_pr[k][n+32]);
            g_aPi [bp] = pk2(s_pi[k][n],  s_pi[k][n+32]);
            g_aPin[bp] = pk2(-s_pi[k][n], -s_pi[k][n+32]);
        }
    }
}

// ---------------- pw1 (64->32 pointwise, packed) + GN1 stats ----------------
__global__ __launch_bounds__(256) void k_pw1(const float* __restrict__ x,
                                             const float* __restrict__ w,
                                             const float* __restrict__ bias) {
    __shared__ float xs[C1][128];
    __shared__ float wst[C1][34];
    __shared__ float rs[8], rss[8];
    int b = blockIdx.y, t0 = blockIdx.x * 128;
    int tid = threadIdx.x;
    for (int i = tid; i < C1*128; i += 256) {
        int c = i >> 7, tt = i & 127;
        xs[c][tt] = x[(b*C1 + c)*T1 + t0 + tt];
    }
    for (int i = tid; i < CO*C1; i += 256) {
        int o = i >> 6, c = i & 63;
        wst[c][o] = w[i];
    }
    __syncthreads();
    int tt = tid & 127, half = tid >> 7;
    int ob0 = half * 16;
    ull acc[8];
#pragma unroll
    for (int p = 0; p < 8; p++) acc[p] = pk2(bias[ob0 + 2*p], bias[ob0 + 2*p + 1]);
    for (int c = 0; c < C1; c++) {
        float xv = xs[c][tt];
        ull X = pk2(xv, xv);
#pragma unroll
        for (int p = 0; p < 8; p++) {
            ull wv = *(const ull*)&wst[c][ob0 + 2*p];
            acc[p] = ffma2(wv, X, acc[p]);
        }
    }
    float s = 0.f, ss = 0.f;
#pragma unroll
    for (int p = 0; p < 8; p++) {
        float a0, a1; upk2(acc[p], a0, a1);
        int o = ob0 + 2*p;
        g_u1[(b*CO + o)*T1 + t0 + tt]     = a0;
        g_u1[(b*CO + o + 1)*T1 + t0 + tt] = a1;
        s += a0 + a1; ss += a0*a0 + a1*a1;
    }
#pragma unroll
    for (int off = 16; off; off >>= 1) {
        s  += __shfl_xor_sync(0xffffffffu, s,  off);
        ss += __shfl_xor_sync(0xffffffffu, ss, off);
    }
    int wid = tid >> 5;
    if ((tid & 31) == 0) { rs[wid] = s; rss[wid] = ss; }
    __syncthreads();
    if (tid == 0) {
        float a = 0.f, q = 0.f;
        for (int i = 0; i < 8; i++) { a += rs[i]; q += rss[i]; }
        atomicAdd(&g_st1[b*2],     a);
        atomicAdd(&g_st1[b*2 + 1], q);
    }
}

// ---- fused GN1-apply + GLU(time) + SiLU + depthwise conv (k=32) + GN2 stats ----
__global__ __launch_bounds__(256) void k_dwf(const float* __restrict__ w,
                                             const float* __restrict__ bias,
                                             const float* __restrict__ g1,
                                             const float* __restrict__ b1) {
    __shared__ float us[1024 + 36];
    __shared__ float wk[32];
    __shared__ float rs[8], rss[8];
    int t0 = blockIdx.x * 1024, c = blockIdx.y, b = blockIdx.z;
    int tid = threadIdx.x;
    if (tid < 32) wk[tid] = w[c*32 + tid];
    float n1 = (float)(CO * T1);
    float m1   = g_st1[b*2] / n1;
    float var1 = g_st1[b*2 + 1] / n1 - m1*m1;
    float rstd1 = rsqrtf(var1 + EPSF);
    float sc = rstd1 * g1[c], sh = b1[c] - m1 * sc;
    const float* base = g_u1 + (b*CO + c)*T1;
    for (int i = tid; i < 1060; i += 256) {
        int gi = t0 - 1 + i;
        float v = 0.f;
        if (gi >= 0 && gi < T2) {
            float ga = fmaf(base[gi],      sc, sh);
            float gb = fmaf(base[gi + T2], sc, sh);
            v = ga / (1.f + __expf(-gb));
            v = v / (1.f + __expf(-v));
        }
        us[i] = v;
    }
    __syncthreads();
    int tt = tid * 4;
    float uw[36];
#pragma unroll
    for (int q = 0; q < 9; q++) {
        float4 v = *(const float4*)&us[tt + q*4];
        uw[q*4+0] = v.x; uw[q*4+1] = v.y; uw[q*4+2] = v.z; uw[q*4+3] = v.w;
    }
    float bc = bias[c];
    float a0 = bc, a1 = bc, a2 = bc, a3 = bc;
#pragma unroll
    for (int k = 0; k < 32; k++) {
        float wv = wk[k];
        a0 = fmaf(wv, uw[k],     a0);
        a1 = fmaf(wv, uw[k + 1], a1);
        a2 = fmaf(wv, uw[k + 2], a2);
        a3 = fmaf(wv, uw[k + 3], a3);
    }
    float s = 0.f, ss = 0.f;
    float* dst = g_u2 + (b*CO + c)*T3 + t0 + tt;
    float av[4] = {a0, a1, a2, a3};
#pragma unroll
    for (int r = 0; r < 4; r++) {
        int t = t0 + tt + r;
        if (t < T3) { dst[r] = av[r]; s += av[r]; ss += av[r]*av[r]; }
    }
#pragma unroll
    for (int off = 16; off; off >>= 1) {
        s  += __shfl_xor_sync(0xffffffffu, s,  off);
        ss += __shfl_xor_sync(0xffffffffu, ss, off);
    }
    int wid = tid >> 5;
    if ((tid & 31) == 0) { rs[wid] = s; rss[wid] = ss; }
    __syncthreads();
    if (tid == 0) {
        float a = 0.f, q = 0.f;
        for (int i = 0; i < 8; i++) { a += rs[i]; q += rss[i]; }
        atomicAdd(&g_st2[b*2],     a);
        atomicAdd(&g_st2[b*2 + 1], q);
    }
}

// ---------------- precompute fused (enc ∘ pw2) matrix (parallel) ----------------
__global__ __launch_bounds__(256) void k_prep(const float* __restrict__ pw2w,
                                              const float* __restrict__ pw2b,
                                              const float* __restrict__ encw,
                                              const float* __restrict__ encb) {
    int i = blockIdx.x * 256 + threadIdx.x;
    if (i < HH*CO) {
        int d = i >> 5, cp = i & 31;
        float acc = 0.f;
#pragma unroll 8
        for (int c = 0; c < CO; c++)
            acc = fmaf(encw[c*HH + d], pw2w[c*CO + cp], acc);
        g_Wm[i] = acc;
    } else if (i < HH*CO + HH) {
        int d = i - HH*CO;
        float acc = encb[d];
#pragma unroll 8
        for (int c = 0; c < CO; c++)
            acc = fmaf(encw[c*HH + d], pw2b[c], acc);
        g_bv[d] = acc;
    }
}

// ---------------- GN2 apply + fused pw2∘enc -> h (packed) ----------------
__global__ __launch_bounds__(256) void k_enc(const float* __restrict__ g2,
                                             const float* __restrict__ b2) {
    __shared__ float un[CO][128];
    __shared__ float Wse[CO][66];
    int b = blockIdx.y, t0 = blockIdx.x * 128;
    int tid = threadIdx.x;
    float n = (float)(CO * T3);
    float m   = g_st2[b*2] / n;
    float var = g_st2[b*2 + 1] / n - m*m;
    float rstd = rsqrtf(var + EPSF);
    for (int i = tid; i < CO*128; i += 256) {
        int c = i >> 7, tt = i & 127;
        int t = t0 + tt;
        float v = (t < T3) ? g_u2[(b*CO + c)*T3 + t] : 0.f;
        un[c][tt] = (v - m) * rstd * g2[c] + b2[c];
    }
    for (int i = tid; i < HH*CO; i += 256) {
        int d = i >> 5, c = i & 31;
        Wse[c][d] = g_Wm[i];
    }
    __syncthreads();
    int tt = tid & 127, dg = tid >> 7;
    int d0 = dg * 32;
    ull acc[16];
#pragma unroll
    for (int p = 0; p < 16; p++) acc[p] = pk2(g_bv[d0 + 2*p], g_bv[d0 + 2*p + 1]);
    for (int c = 0; c < CO; c++) {
        float uv = un[c][tt];
        ull U = pk2(uv, uv);
#pragma unroll
        for (int p = 0; p < 16; p++) {
            ull wv = *(const ull*)&Wse[c][d0 + 2*p];
            acc[p] = ffma2(wv, U, acc[p]);
        }
    }
    int t = t0 + tt;
    if (t < T3) {
#pragma unroll
        for (int p = 0; p < 16; p++) {
            float a0, a1; upk2(acc[p], a0, a1);
            g_h[(b*HH + d0 + 2*p)*T3 + t]     = a0;
            g_h[(b*HH + d0 + 2*p + 1)*T3 + t] = a1;
        }
    }
}

// ---------------- fused S4D scan: carry phase + flag handshake + output ----------------
__global__ __launch_bounds__(128) void k_sc(const float* __restrict__ D, int lay) {
    __shared__ float ps[4][32*33];
    int lane = threadIdx.x & 31, wl = threadIdx.x >> 5;
    int wg = blockIdx.x * 4 + wl;            // 0..8191
    int bh = wg & 1023, p = wg >> 10;        // seg p in 0..7
    int b = bh >> 6, h = bh & 63;
    int cbase = (lay*HH + h)*32 + lane;
    ull Ar  = g_pAr [cbase];
    ull Ai  = g_pAi [cbase];
    ull NAi = g_pAin[cbase];
    ull CcR = g_pCr [cbase];
    ull CcI = g_pCi [cbase];
    ull CcIn= g_pCin[cbase];
    float Dh = D[lay*HH + h];
    int t0 = p * SEG;
    int len = min(SEG, T3 - t0);             // 256, or 227 for p=7
    const float* uin = g_h + (b*HH + h)*T3 + t0;
    float* yo = g_y + (b*HH + h)*T3 + t0;
    // load full segment's u into registers (zero-padded tail)
    float u[8];
#pragma unroll
    for (int ci = 0; ci < 8; ci++) {
        int t = ci*32 + lane;
        u[ci] = (t < len) ? uin[t] : 0.f;
    }
    // ---- phase 1: compute + publish this segment's carry (segments 0..6) ----
    if (p < 7) {
        ull Sr = 0ull, Si = 0ull;
#pragma unroll
        for (int ci = 0; ci < 8; ci++) {
            float uc = u[ci];
#pragma unroll
            for (int j = 0; j < 32; j++) {
                float uj = __shfl_sync(0xffffffffu, uc, j);
                ull U = pk2(uj, uj);
                ull t = ffma2(NAi, Si, U);
                ull m = fmul2(Ai, Sr);
                Sr = ffma2(Ar, Sr, t);
                Si = ffma2(Ar, Si, m);
            }
        }
        int ci2 = (p*BB*HH + bh)*32 + lane;
        g_carR[ci2] = Sr;
        g_carI[ci2] = Si;
        __syncwarp();
        __threadfence();
        if (lane == 0)
            *((volatile int*)&g_flag[(lay*7 + p)*BB*HH + bh]) = 1;
    }
    // ---- wait for predecessors' carries ----
    for (int q = 0; q < p; q++) {
        volatile int* f = &g_flag[(lay*7 + q)*BB*HH + bh];
        while (*f == 0) __nanosleep(64);
    }
    __threadfence();
    // ---- reconstruct segment-start state ----
    ull Sr = 0ull, Si = 0ull;
    for (int q = 0; q < p; q++) {
        int k = p - 1 - q;
        int bp = ((lay*HH + h)*7 + k)*32 + lane;
        ull aPr  = g_aPr [bp];
        ull aPi  = g_aPi [bp];
        ull aPin = g_aPin[bp];
        int ci2 = (q*BB*HH + bh)*32 + lane;
        ull CqR = g_carR[ci2], CqI = g_carI[ci2];
        Sr = ffma2(aPr,  CqR, Sr);
        Sr = ffma2(aPin, CqI, Sr);
        Si = ffma2(aPr,  CqI, Si);
        Si = ffma2(aPi,  CqR, Si);
    }
    // z = Cc ⊙ S
    ull zr = ffma2(CcR, Sr, fmul2(CcIn, Si));
    ull zi = ffma2(CcR, Si, fmul2(CcI,  Sr));
    float* psw = ps[wl];
    // ---- phase 2: output scan, chunks 0..6 always full ----
#pragma unroll
    for (int ci = 0; ci < 7; ci++) {
        float uc = u[ci];
#pragma unroll
        for (int j = 0; j < 32; j++) {
            float uj = __shfl_sync(0xffffffffu, uc, j);
            ull U = pk2(uj, uj);
            ull t1 = ffma2(NAi, zi, fmul2(CcR, U));
            ull t3 = ffma2(Ai,  zr, fmul2(CcI, U));
            zr = ffma2(Ar, zr, t1);
            zi = ffma2(Ar, zi, t3);
            float lo, hi; upk2(zr, lo, hi);
            psw[lane*33 + j] = lo + hi;
        }
        __syncwarp();
        {
            float acc = psw[lane];
#pragma unroll
            for (int k = 1; k < 32; k++) acc += psw[k*33 + lane];
            float yv = fmaf(Dh, uc, acc);
            yv = 0.5f * yv * (1.f + erff(yv * 0.70710678118f));
            yo[ci*32 + lane] = yv;
        }
        __syncwarp();
    }
    // ---- tail chunk 7 (lc = 32 or 3) ----
    {
        int lc = len - 224;
        float uc = u[7];
        for (int j = 0; j < lc; j++) {
            float uj = __shfl_sync(0xffffffffu, uc, j);
            ull U = pk2(uj, uj);
            ull t1 = ffma2(NAi, zi, fmul2(CcR, U));
            ull t3 = ffma2(Ai,  zr, fmul2(CcI, U));
            zr = ffma2(Ar, zr, t1);
            zi = ffma2(Ar, zi, t3);
            float lo, hi; upk2(zr, lo, hi);
            psw[lane*33 + j] = lo + hi;
        }
        __syncwarp();
        if (lane < lc) {
            float acc = psw[lane];
#pragma unroll
            for (int k = 1; k < 32; k++) acc += psw[k*33 + lane];
            float yv = fmaf(Dh, uc, acc);
            yv = 0.5f * yv * (1.f + erff(yv * 0.70710678118f));
            yo[224 + lane] = yv;
        }
    }
}

// ---- mixer: smem-tiled ow GEMM (packed) + GLU(ch) + residual + LN(ch) ----
__global__ __launch_bounds__(256) void k_mix(const float* __restrict__ ow,
                                             const float* __restrict__ ob,
                                             const float* __restrict__ lg,
                                             const float* __restrict__ lb, int lay) {
    __shared__ float Ws[64][130];
    __shared__ float ys[64][32];
    __shared__ float rsum[8][32], rss2[8][32];
    __shared__ float mu[32], rstd[32];
    int b = blockIdx.y, t0 = blockIdx.x * 32;
    int tid = threadIdx.x;
    const float* owl = ow + lay*2*HH*HH;
    const float* obl = ob + lay*2*HH;
    for (int i = tid; i < 2*HH*HH; i += 256) {
        int j = i >> 6, k = i & 63;
        Ws[k][j] = owl[i];
    }
    for (int i = tid; i < HH*32; i += 256) {
        int ch = i >> 5, tt = i & 31;
        int t = t0 + tt;
        ys[ch][tt] = (t < T3) ? g_y[(b*HH + ch)*T3 + t] : 0.f;
    }
    __syncthreads();
    int chgrp = tid >> 3, tgrp = tid & 7;
    int ch0 = chgrp * 2, tsub = tgrp * 4;
    ull accA[4], accB[4];
    {
        ull ia = pk2(obl[ch0],      obl[ch0 + 1]);
        ull ib = pk2(obl[ch0 + 64], obl[ch0 + 65]);
#pragma unroll
        for (int t = 0; t < 4; t++) { accA[t] = ia; accB[t] = ib; }
    }
#pragma unroll 4
    for (int k = 0; k < 64; k++) {
        ull wa = *(const ull*)&Ws[k][ch0];
        ull wb = *(const ull*)&Ws[k][ch0 + 64];
        float4 yv = *(const float4*)&ys[k][tsub];
        ull y0 = pk2(yv.x, yv.x), y1 = pk2(yv.y, yv.y);
        ull y2 = pk2(yv.z, yv.z), y3 = pk2(yv.w, yv.w);
        accA[0] = ffma2(wa, y0, accA[0]);  accB[0] = ffma2(wb, y0, accB[0]);
        accA[1] = ffma2(wa, y1, accA[1]);  accB[1] = ffma2(wb, y1, accB[1]);
        accA[2] = ffma2(wa, y2, accA[2]);  accB[2] = ffma2(wb, y2, accB[2]);
        accA[3] = ffma2(wa, y3, accA[3]);  accB[3] = ffma2(wb, y3, accB[3]);
    }
    __syncthreads();
    float zr0[4], zr1[4];
#pragma unroll
    for (int t = 0; t < 4; t++) {
        int tg = t0 + tsub + t;
        float oa0, oa1, og0, og1;
        upk2(accA[t], oa0, oa1);
        upk2(accB[t], og0, og1);
        float h0 = 0.f, h1 = 0.f;
        if (tg < T3) {
            h0 = g_h[(b*HH + ch0)*T3 + tg];
            h1 = g_h[(b*HH + ch0 + 1)*T3 + tg];
        }
        float z0 = oa0 / (1.f + __expf(-og0)) + h0;
        float z1 = oa1 / (1.f + __expf(-og1)) + h1;
        zr0[t] = z0; zr1[t] = z1;
        ys[ch0][tsub + t]     = z0;
        ys[ch0 + 1][tsub + t] = z1;
    }
    __syncthreads();
    {
        int grp = tid >> 5, tsel = tid & 31;
        float s = 0.f, ss = 0.f;
#pragma unroll
        for (int q = 0; q < 8; q++) {
            float v = ys[grp*8 + q][tsel];
            s += v; ss += v*v;
        }
        rsum[grp][tsel] = s; rss2[grp][tsel] = ss;
    }
    __syncthreads();
    if (tid < 32) {
        float s = 0.f, ss = 0.f;
#pragma unroll
        for (int g = 0; g < 8; g++) { s += rsum[g][tid]; ss += rss2[g][tid]; }
        float m = s / 64.f;
        float var = ss / 64.f - m*m;
        mu[tid] = m; rstd[tid] = rsqrtf(var + EPSF);
    }
    __syncthreads();
    float lg0 = lg[lay*HH + ch0], lg1 = lg[lay*HH + ch0 + 1];
    float lb0 = lb[lay*HH + ch0], lb1 = lb[lay*HH + ch0 + 1];
#pragma unroll
    for (int t = 0; t < 4; t++) {
        int tg = t0 + tsub + t;
        if (tg < T3) {
            float m = mu[tsub + t], r = rstd[tsub + t];
            g_h[(b*HH + ch0)*T3 + tg]     = (zr0[t] - m) * r * lg0 + lb0;
            g_h[(b*HH + ch0 + 1)*T3 + tg] = (zr1[t] - m) * r * lg1 + lb1;
        }
    }
}

// ---------------- decoder: tiled packed GEMM (b,d,t)x(d,o) -> (b,t,o) ----------------
__global__ __launch_bounds__(256) void k_dec(const float* __restrict__ dw,
                                             const float* __restrict__ db,
                                             float* __restrict__ out) {
    __shared__ float wsd[HH][64];
    __shared__ float hsd[HH][64];
    int o0b = blockIdx.x * 64, t0 = blockIdx.y * 64, b = blockIdx.z;
    int tid = threadIdx.x;
    for (int i = tid; i < HH*64; i += 256) {
        int d = i >> 6, o = i & 63;
        wsd[d][o] = dw[d*DOUT + o0b + o];
    }
    for (int i = tid; i < HH*64; i += 256) {
        int d = i >> 6, tt = i & 63;
        int t = t0 + tt;
        hsd[d][tt] = (t < T3) ? g_h[(b*HH + d)*T3 + t] : 0.f;
    }
    __syncthreads();
    int ogrp = tid & 15, tgrp = tid >> 4;
    int o0 = ogrp * 4, tsub = tgrp * 4;
    ull accA[4], accB[4];
    {
        ull ia = pk2(db[o0b + o0],     db[o0b + o0 + 1]);
        ull ib = pk2(db[o0b + o0 + 2], db[o0b + o0 + 3]);
#pragma unroll
        for (int t = 0; t < 4; t++) { accA[t] = ia; accB[t] = ib; }
    }
#pragma unroll 4
    for (int k = 0; k < HH; k++) {
        ull wa = *(const ull*)&wsd[k][o0];
        ull wb = *(const ull*)&wsd[k][o0 + 2];
        float4 hv = *(const float4*)&hsd[k][tsub];
        ull h0 = pk2(hv.x, hv.x), h1 = pk2(hv.y, hv.y);
        ull h2 = pk2(hv.z, hv.z), h3 = pk2(hv.w, hv.w);
        accA[0] = ffma2(wa, h0, accA[0]);  accB[0] = ffma2(wb, h0, accB[0]);
        accA[1] = ffma2(wa, h1, accA[1]);  accB[1] = ffma2(wb, h1, accB[1]);
        accA[2] = ffma2(wa, h2, accA[2]);  accB[2] = ffma2(wb, h2, accB[2]);
        accA[3] = ffma2(wa, h3, accA[3]);  accB[3] = ffma2(wb, h3, accB[3]);
    }
#pragma unroll
    for (int t = 0; t < 4; t++) {
        int tg = t0 + tsub + t;
        if (tg < T3) {
            float4 o4;
            upk2(accA[t], o4.x, o4.y);
            upk2(accB[t], o4.z, o4.w);
            *(float4*)&out[((size_t)(b*T3 + tg))*DOUT + o0b + o0] = o4;
        }
    }
}

// ---------------- launcher ----------------
extern "C" void kernel_launch(void* const* d_in, const int* in_sizes, int n_in,
                              void* d_out, int out_size) {
    const float* x      = (const float*)d_in[0];
    const float* pw1w   = (const float*)d_in[1];
    const float* pw1b   = (const float*)d_in[2];
    const float* gn1g   = (const float*)d_in[3];
    const float* gn1b   = (const float*)d_in[4];
    const float* dww    = (const float*)d_in[5];
    const float* dwb    = (const float*)d_in[6];
    const float* gn2g   = (const float*)d_in[7];
    const float* gn2b   = (const float*)d_in[8];
    const float* pw2w   = (const float*)d_in[9];
    const float* pw2b   = (const float*)d_in[10];
    const float* encw   = (const float*)d_in[11];
    const float* encb   = (const float*)d_in[12];
    const float* logdt  = (const float*)d_in[13];
    const float* logA   = (const float*)d_in[14];
    const float* Aim    = (const float*)d_in[15];
    const float* Cre    = (const float*)d_in[16];
    const float* Cim    = (const float*)d_in[17];
    const float* s4D    = (const float*)d_in[18];
    const float* s4ow   = (const float*)d_in[19];
    const float* s4ob   = (const float*)d_in[20];
    const float* lng    = (const float*)d_in[21];
    const float* lnb    = (const float*)d_in[22];
    const float* decw   = (const float*)d_in[23];
    const float* decb   = (const float*)d_in[24];
    float* out = (float*)d_out;

    k_s4c<<<dim3(HH, NL), 64>>>(logdt, logA, Aim, Cre, Cim);
    k_pw1<<<dim3(T1/128, BB), 256>>>(x, pw1w, pw1b);
    k_dwf<<<dim3(2, CO, BB), 256>>>(dww, dwb, gn1g, gn1b);
    k_prep<<<9, 256>>>(pw2w, pw2b, encw, encb);
    k_enc<<<dim3(16, BB), 256>>>(gn2g, gn2b);
    for (int l = 0; l < NL; l++) {
        k_sc<<<(BB*HH*NSEG)/4, 128>>>(s4D, l);
        k_mix<<<dim3(64, BB), 256>>>(s4ow, s4ob, lng, lnb, l);
    }
    k_dec<<<dim3(DOUT/64, 32, BB), 256>>>(decw, decb, out);
}